// round 12
// baseline (speedup 1.0000x reference)
#include <cuda_runtime.h>
#include <cstdint>

// ---------------------------------------------------------------------------
// Problem constants
// ---------------------------------------------------------------------------
#define B_DIM 8
#define L_DIM 1024
#define D_MODEL 1024
#define N_HEADS 16
#define D_KEYS 64
#define D_LLM 4096
#define HD 1024           // N_HEADS * D_KEYS
#define ML (B_DIM * L_DIM) // 8192

// Scratch (device globals: allocation-free contract)
__device__ float g_q[ML * HD];
__device__ float g_k[1024 * HD];
__device__ float g_v[1024 * HD];
__device__ float g_attn[ML * HD];
// tf32-formatted copies of the read-only inputs
__device__ float g_tgt[ML * D_MODEL];     // 32 MB
__device__ float g_src[1024 * D_LLM];     // 16 MB
__device__ float g_val[1024 * D_LLM];     // 16 MB
__device__ float g_wq[D_MODEL * HD];      // 4 MB
__device__ float g_wk[D_LLM * HD];        // 16 MB
__device__ float g_wv[D_LLM * HD];        // 16 MB
__device__ float g_wo[HD * D_LLM];        // 16 MB

__device__ __forceinline__ uint32_t f32_to_tf32(float x) {
    uint32_t r;
    asm("cvt.rna.tf32.f32 %0, %1;" : "=r"(r) : "f"(x));
    return r;
}
__device__ __forceinline__ uint32_t smem_u32(const void* p) {
    uint32_t a;
    asm("{ .reg .u64 t; cvta.to.shared.u64 t, %1; cvt.u32.u64 %0, t; }" : "=r"(a) : "l"(p));
    return a;
}
__device__ __forceinline__ void cp_async16(uint32_t dst, const void* src, bool pred) {
    const int sz = pred ? 16 : 0;   // src-size 0 -> 16B zero-fill
    asm volatile("cp.async.cg.shared.global [%0], [%1], 16, %2;"
                 :: "r"(dst), "l"(src), "r"(sz) : "memory");
}
__device__ __forceinline__ void cp_async_commit() {
    asm volatile("cp.async.commit_group;" ::: "memory");
}
template <int N>
__device__ __forceinline__ void cp_async_wait() {
    asm volatile("cp.async.wait_group %0;" :: "n"(N) : "memory");
}

#define MMA_TF32(d, a, b0v, b1v)                                               \
    asm volatile(                                                              \
        "mma.sync.aligned.m16n8k8.row.col.f32.tf32.tf32.f32 "                  \
        "{%0,%1,%2,%3}, {%4,%5,%6,%7}, {%8,%9}, {%0,%1,%2,%3};"                \
        : "+f"((d)[0]), "+f"((d)[1]), "+f"((d)[2]), "+f"((d)[3])               \
        : "r"((a)[0]), "r"((a)[1]), "r"((a)[2]), "r"((a)[3]),                  \
          "r"(b0v), "r"(b1v))

// ---------------------------------------------------------------------------
// Pre-pass: convert 7 read-only inputs to tf32-formatted fp32 (bit-identical
// to the cvt previously done inside the GEMM loops).
// grid = (128, 7), 256 threads, grid-stride in x.
// ---------------------------------------------------------------------------
__global__ __launch_bounds__(256)
void cvt_prep_kernel(const float* s0, float* d0, int n0,
                     const float* s1, float* d1, int n1,
                     const float* s2, float* d2, int n2,
                     const float* s3, float* d3, int n3,
                     const float* s4, float* d4, int n4,
                     const float* s5, float* d5, int n5,
                     const float* s6, float* d6, int n6)
{
    const float* s; float* d; int n;
    switch (blockIdx.y) {
        case 0: s = s0; d = d0; n = n0; break;
        case 1: s = s1; d = d1; n = n1; break;
        case 2: s = s2; d = d2; n = n2; break;
        case 3: s = s3; d = d3; n = n3; break;
        case 4: s = s4; d = d4; n = n4; break;
        case 5: s = s5; d = d5; n = n5; break;
        default: s = s6; d = d6; n = n6; break;
    }
    const int n4v = n >> 2;
    const int stride = gridDim.x * blockDim.x;
    for (int i = blockIdx.x * blockDim.x + threadIdx.x; i < n4v; i += stride) {
        float4 v = ((const float4*)s)[i];
        uint4 o;
        o.x = f32_to_tf32(v.x); o.y = f32_to_tf32(v.y);
        o.z = f32_to_tf32(v.z); o.w = f32_to_tf32(v.w);
        ((uint4*)d)[i] = o;
    }
}

// ---------------------------------------------------------------------------
// TF32 tensor-core GEMM, cp.async 4-stage pipeline. Inputs are PRE-CONVERTED
// (tf32-formatted fp32) -> NO cvt in the inner loop.
// CVT_OUT: store tf32-formatted output (for tensors consumed by later MMAs).
// 128x128 CTA tile, BK=8, 256 threads (8 warps, 2x4), warp tile 64x32.
// ---------------------------------------------------------------------------
#define BMT 128
#define BNT 128
#define BKT 8
#define APITCH 12
#define BPITCH 136
#define STAGES 4

template <bool CVT_OUT>
__device__ __forceinline__
void gemm_body(const float* __restrict__ A, const float* __restrict__ W,
               const float* __restrict__ bias, float* __restrict__ C,
               int M, int N, int K)
{
    __shared__ float As[STAGES][BMT][APITCH];
    __shared__ float Bs[STAGES][BKT][BPITCH];

    const int tid  = threadIdx.x;
    const int lane = tid & 31;
    const int warp = tid >> 5;
    const int wm = (warp >> 2) * 64;
    const int wn = (warp & 3) * 32;
    const int grp = lane >> 2;
    const int tig = lane & 3;

    const int m0 = blockIdx.y * BMT;
    const int n0 = blockIdx.x * BNT;

    const int a_row = tid >> 1;
    const int a_k   = (tid & 1) << 2;
    const int b_k   = tid >> 5;
    const int b_n   = (tid & 31) << 2;

    const bool a_ok = (m0 + a_row) < M;
    const float* a_src = A + (size_t)(m0 + a_row) * K + a_k;
    const float* b_src = W + (size_t)b_k * N + n0 + b_n;

    const uint32_t a_dst0 = smem_u32(&As[0][a_row][a_k]);
    const uint32_t b_dst0 = smem_u32(&Bs[0][b_k][b_n]);
    const uint32_t a_stride = (uint32_t)(BMT * APITCH * 4);
    const uint32_t b_stride = (uint32_t)(BKT * BPITCH * 4);

    float acc[4][4][4];
    #pragma unroll
    for (int i = 0; i < 4; i++)
        #pragma unroll
        for (int j = 0; j < 4; j++)
            #pragma unroll
            for (int r = 0; r < 4; r++) acc[i][j][r] = 0.0f;

    const int nk = K / BKT;

    #pragma unroll
    for (int s = 0; s < STAGES - 1; s++) {
        if (s < nk) {
            cp_async16(a_dst0 + s * a_stride, a_src + (size_t)s * BKT, a_ok);
            cp_async16(b_dst0 + s * b_stride, b_src + (size_t)s * BKT * N, true);
        }
        cp_async_commit();
    }

    for (int kt = 0; kt < nk; kt++) {
        const int cur = kt & (STAGES - 1);
        cp_async_wait<STAGES - 2>();
        __syncthreads();

        {
            const int kn = kt + STAGES - 1;
            if (kn < nk) {
                const int st = kn & (STAGES - 1);
                cp_async16(a_dst0 + st * a_stride, a_src + (size_t)kn * BKT, a_ok);
                cp_async16(b_dst0 + st * b_stride, b_src + (size_t)kn * BKT * N, true);
            }
            cp_async_commit();
        }

        // fragments: plain loads (data already tf32-formatted)
        uint32_t af[4][4], bf[4][2];
        #pragma unroll
        for (int tm = 0; tm < 4; tm++) {
            const int rb = wm + tm * 16 + grp;
            af[tm][0] = __float_as_uint(As[cur][rb][tig]);
            af[tm][1] = __float_as_uint(As[cur][rb + 8][tig]);
            af[tm][2] = __float_as_uint(As[cur][rb][tig + 4]);
            af[tm][3] = __float_as_uint(As[cur][rb + 8][tig + 4]);
        }
        #pragma unroll
        for (int tn = 0; tn < 4; tn++) {
            const int nb = wn + tn * 8 + grp;
            bf[tn][0] = __float_as_uint(Bs[cur][tig][nb]);
            bf[tn][1] = __float_as_uint(Bs[cur][tig + 4][nb]);
        }

        #pragma unroll
        for (int tm = 0; tm < 4; tm++)
            #pragma unroll
            for (int tn = 0; tn < 4; tn++)
                MMA_TF32(acc[tm][tn], af[tm], bf[tn][0], bf[tn][1]);
        // single barrier per iter (top of loop)
    }

    // ---- epilogue: bias + store (optionally tf32-formatted) ----
    #pragma unroll
    for (int tm = 0; tm < 4; tm++) {
        const int row  = m0 + wm + tm * 16 + grp;
        const int row2 = row + 8;
        #pragma unroll
        for (int tn = 0; tn < 4; tn++) {
            const int col = n0 + wn + tn * 8 + 2 * tig;
            const float b0v = bias[col];
            const float b1v = bias[col + 1];
            float o0 = acc[tm][tn][0] + b0v, o1 = acc[tm][tn][1] + b1v;
            float o2 = acc[tm][tn][2] + b0v, o3 = acc[tm][tn][3] + b1v;
            if (CVT_OUT) {
                o0 = __uint_as_float(f32_to_tf32(o0));
                o1 = __uint_as_float(f32_to_tf32(o1));
                o2 = __uint_as_float(f32_to_tf32(o2));
                o3 = __uint_as_float(f32_to_tf32(o3));
            }
            if (row < M)  *(float2*)(C + (size_t)row * N + col)  = make_float2(o0, o1);
            if (row2 < M) *(float2*)(C + (size_t)row2 * N + col) = make_float2(o2, o3);
        }
    }
}

__global__ __launch_bounds__(256, 2)
void gemm_tf32_out_kernel(const float* __restrict__ A, const float* __restrict__ W,
                          const float* __restrict__ bias, float* __restrict__ C,
                          int M, int N, int K)
{
    gemm_body<false>(A, W, bias, C, M, N, K);
}

__global__ __launch_bounds__(256, 2)
void gemm_tf32_q_kernel(const float* __restrict__ A, const float* __restrict__ W,
                        const float* __restrict__ bias, float* __restrict__ C,
                        int M, int N, int K)
{
    gemm_body<true>(A, W, bias, C, M, N, K);
}

__global__ __launch_bounds__(256, 2)
void gemm_tf32_dual_kernel(const float* __restrict__ A0, const float* __restrict__ W0,
                           const float* __restrict__ b0, float* __restrict__ C0,
                           const float* __restrict__ A1, const float* __restrict__ W1,
                           const float* __restrict__ b1, float* __restrict__ C1,
                           int M, int N, int K)
{
    if (blockIdx.z == 0) gemm_body<true>(A0, W0, b0, C0, M, N, K);
    else                 gemm_body<true>(A1, W1, b1, C1, M, N, K);
}

// ---------------------------------------------------------------------------
// Tensor-core flash attention (tf32 m16n8k8), head_dim = 64.
// One block per (b, h, 128-query tile). 256 threads = 8 warps.
// q/k/v arrive PRE-CONVERTED (tf32-formatted) -> staging is plain bit-copy.
// Output written tf32-formatted for the O-projection.
// ---------------------------------------------------------------------------
#define QT 128
#define QK_PITCH 68
#define V_PITCH  72
#define P_PITCH  72

__global__ __launch_bounds__(256, 2)
void attn_tc_kernel(const float* __restrict__ q, const float* __restrict__ k,
                    const float* __restrict__ v, float* __restrict__ o_out,
                    const float* __restrict__ alpha, const float* __restrict__ beta,
                    int S)
{
    extern __shared__ uint32_t smu[];
    uint32_t* Ks = smu;
    uint32_t* Vs = Ks + 64 * QK_PITCH;
    uint32_t* Ps = Vs + 64 * V_PITCH;

    const int tid  = threadIdx.x;
    const int lane = tid & 31;
    const int warp = tid >> 5;
    const int grp  = lane >> 2;
    const int tig  = lane & 3;

    const int l0 = blockIdx.x * QT;
    const int b  = blockIdx.y >> 4;
    const int h  = blockIdx.y & 15;

    const float scale = alpha[0] * beta[0] * 0.125f;

    const float* qbase = q + ((size_t)(b * L_DIM + l0)) * HD + h * D_KEYS;
    #pragma unroll
    for (int p = 0; p < 8; p++) {
        const int idx = p * 256 + tid;
        const int row = idx >> 4;
        const int e4  = (idx & 15) << 2;
        uint4 t = *(const uint4*)(qbase + (size_t)row * HD + e4);
        *(uint4*)(Ps + row * P_PITCH + e4) = t;
    }
    __syncthreads();

    uint32_t qf[8][4];
    {
        const int qrow = warp * 16 + grp;
        #pragma unroll
        for (int ks = 0; ks < 8; ks++) {
            qf[ks][0] = Ps[qrow * P_PITCH + ks * 8 + tig];
            qf[ks][1] = Ps[(qrow + 8) * P_PITCH + ks * 8 + tig];
            qf[ks][2] = Ps[qrow * P_PITCH + ks * 8 + tig + 4];
            qf[ks][3] = Ps[(qrow + 8) * P_PITCH + ks * 8 + tig + 4];
        }
    }

    float m0r = -1e30f, m1r = -1e30f, l0r = 0.0f, l1r = 0.0f;
    float oa[8][4];
    #pragma unroll
    for (int nt = 0; nt < 8; nt++)
        #pragma unroll
        for (int r = 0; r < 4; r++) oa[nt][r] = 0.0f;

    const int nTiles = (S + 63) >> 6;
    for (int ts = 0; ts < nTiles; ts++) {
        const int s0 = ts * 64;
        __syncthreads();

        const float* kb2 = k + (size_t)s0 * HD + h * D_KEYS;
        const float* vb2 = v + (size_t)s0 * HD + h * D_KEYS;
        #pragma unroll
        for (int p = 0; p < 4; p++) {
            const int idx = p * 256 + tid;
            const int j  = idx >> 4;
            const int e4 = (idx & 15) << 2;
            uint4 tk, tv;
            if (s0 + j < S) {
                tk = *(const uint4*)(kb2 + (size_t)j * HD + e4);
                tv = *(const uint4*)(vb2 + (size_t)j * HD + e4);
            } else {
                tk = make_uint4(0u, 0u, 0u, 0u);
                tv = tk;
            }
            *(uint4*)(Ks + j * QK_PITCH + e4) = tk;
            *(uint4*)(Vs + j * V_PITCH + e4) = tv;
        }
        __syncthreads();

        float sc[8][4];
        #pragma unroll
        for (int nt = 0; nt < 8; nt++)
            #pragma unroll
            for (int r = 0; r < 4; r++) sc[nt][r] = 0.0f;

        #pragma unroll
        for (int ks = 0; ks < 8; ks++) {
            #pragma unroll
            for (int nt = 0; nt < 8; nt++) {
                const uint32_t b0v = Ks[(nt * 8 + grp) * QK_PITCH + ks * 8 + tig];
                const uint32_t b1v = Ks[(nt * 8 + grp) * QK_PITCH + ks * 8 + tig + 4];
                MMA_TF32(sc[nt], qf[ks], b0v, b1v);
            }
        }

        #pragma unroll
        for (int nt = 0; nt < 8; nt++) {
            const int c0 = s0 + nt * 8 + 2 * tig;
            const bool v0 = c0 < S, v1 = (c0 + 1) < S;
            sc[nt][0] = v0 ? sc[nt][0] * scale : -1e30f;
            sc[nt][1] = v1 ? sc[nt][1] * scale : -1e30f;
            sc[nt][2] = v0 ? sc[nt][2] * scale : -1e30f;
            sc[nt][3] = v1 ? sc[nt][3] * scale : -1e30f;
        }

        float mt0 = -1e30f, mt1 = -1e30f;
        #pragma unroll
        for (int nt = 0; nt < 8; nt++) {
            mt0 = fmaxf(mt0, fmaxf(sc[nt][0], sc[nt][1]));
            mt1 = fmaxf(mt1, fmaxf(sc[nt][2], sc[nt][3]));
        }
        mt0 = fmaxf(mt0, __shfl_xor_sync(0xffffffffu, mt0, 1));
        mt0 = fmaxf(mt0, __shfl_xor_sync(0xffffffffu, mt0, 2));
        mt1 = fmaxf(mt1, __shfl_xor_sync(0xffffffffu, mt1, 1));
        mt1 = fmaxf(mt1, __shfl_xor_sync(0xffffffffu, mt1, 2));

        const float mn0 = fmaxf(m0r, mt0);
        const float mn1 = fmaxf(m1r, mt1);
        const float fac0 = __expf(m0r - mn0);
        const float fac1 = __expf(m1r - mn1);
        m0r = mn0; m1r = mn1;
        l0r *= fac0; l1r *= fac1;
        #pragma unroll
        for (int nt = 0; nt < 8; nt++) {
            oa[nt][0] *= fac0; oa[nt][1] *= fac0;
            oa[nt][2] *= fac1; oa[nt][3] *= fac1;
        }

        float rs0 = 0.0f, rs1 = 0.0f;
        #pragma unroll
        for (int nt = 0; nt < 8; nt++) {
            sc[nt][0] = __expf(sc[nt][0] - mn0);
            sc[nt][1] = __expf(sc[nt][1] - mn0);
            sc[nt][2] = __expf(sc[nt][2] - mn1);
            sc[nt][3] = __expf(sc[nt][3] - mn1);
            rs0 += sc[nt][0] + sc[nt][1];
            rs1 += sc[nt][2] + sc[nt][3];
        }
        rs0 += __shfl_xor_sync(0xffffffffu, rs0, 1);
        rs0 += __shfl_xor_sync(0xffffffffu, rs0, 2);
        rs1 += __shfl_xor_sync(0xffffffffu, rs1, 1);
        rs1 += __shfl_xor_sync(0xffffffffu, rs1, 2);
        l0r += rs0; l1r += rs1;

        {
            const int pr0 = warp * 16 + grp;
            #pragma unroll
            for (int nt = 0; nt < 8; nt++) {
                uint2 p01 = make_uint2(f32_to_tf32(sc[nt][0]), f32_to_tf32(sc[nt][1]));
                uint2 p23 = make_uint2(f32_to_tf32(sc[nt][2]), f32_to_tf32(sc[nt][3]));
                *(uint2*)&Ps[pr0 * P_PITCH + nt * 8 + 2 * tig] = p01;
                *(uint2*)&Ps[(pr0 + 8) * P_PITCH + nt * 8 + 2 * tig] = p23;
            }
        }
        __syncwarp();

        #pragma unroll
        for (int ks = 0; ks < 8; ks++) {
            uint32_t af[4];
            const int pr0 = warp * 16 + grp;
            af[0] = Ps[pr0 * P_PITCH + ks * 8 + tig];
            af[1] = Ps[(pr0 + 8) * P_PITCH + ks * 8 + tig];
            af[2] = Ps[pr0 * P_PITCH + ks * 8 + tig + 4];
            af[3] = Ps[(pr0 + 8) * P_PITCH + ks * 8 + tig + 4];
            #pragma unroll
            for (int nt = 0; nt < 8; nt++) {
                const uint32_t b0v = Vs[(ks * 8 + tig) * V_PITCH + nt * 8 + grp];
                const uint32_t b1v = Vs[(ks * 8 + tig + 4) * V_PITCH + nt * 8 + grp];
                MMA_TF32(oa[nt], af, b0v, b1v);
            }
        }
    }

    // normalize + store, tf32-formatted for the O-projection
    const float inv0 = 1.0f / l0r;
    const float inv1 = 1.0f / l1r;
    float* ob = o_out + ((size_t)(b * L_DIM + l0 + warp * 16 + grp)) * HD + h * D_KEYS;
    #pragma unroll
    for (int nt = 0; nt < 8; nt++) {
        const int col = nt * 8 + 2 * tig;
        uint2 o0 = make_uint2(f32_to_tf32(oa[nt][0] * inv0), f32_to_tf32(oa[nt][1] * inv0));
        uint2 o1 = make_uint2(f32_to_tf32(oa[nt][2] * inv1), f32_to_tf32(oa[nt][3] * inv1));
        *(uint2*)(ob + col) = o0;
        *(uint2*)(ob + (size_t)8 * HD + col) = o1;
    }
}

// ---------------------------------------------------------------------------
// Launch
// ---------------------------------------------------------------------------
extern "C" void kernel_launch(void* const* d_in, const int* in_sizes, int n_in,
                              void* d_out, int out_size)
{
    const float* target = (const float*)d_in[0];
    const float* source = (const float*)d_in[1];
    const float* value  = (const float*)d_in[2];
    const float* Wq = (const float*)d_in[3];
    const float* bq = (const float*)d_in[4];
    const float* Wk = (const float*)d_in[5];
    const float* bk = (const float*)d_in[6];
    const float* Wv = (const float*)d_in[7];
    const float* bv = (const float*)d_in[8];
    const float* Wo = (const float*)d_in[9];
    const float* bo = (const float*)d_in[10];
    const float* alpha = (const float*)d_in[11];
    const float* beta  = (const float*)d_in[12];
    float* out = (float*)d_out;

    const int S = in_sizes[1] / D_LLM;   // 1000

    float *qb, *kb, *vb, *ab;
    float *tgt, *src, *val, *wq, *wk, *wv, *wo;
    cudaGetSymbolAddress((void**)&qb, g_q);
    cudaGetSymbolAddress((void**)&kb, g_k);
    cudaGetSymbolAddress((void**)&vb, g_v);
    cudaGetSymbolAddress((void**)&ab, g_attn);
    cudaGetSymbolAddress((void**)&tgt, g_tgt);
    cudaGetSymbolAddress((void**)&src, g_src);
    cudaGetSymbolAddress((void**)&val, g_val);
    cudaGetSymbolAddress((void**)&wq, g_wq);
    cudaGetSymbolAddress((void**)&wk, g_wk);
    cudaGetSymbolAddress((void**)&wv, g_wv);
    cudaGetSymbolAddress((void**)&wo, g_wo);

    dim3 blk(256);

    // pre-convert all read-only GEMM inputs to tf32-formatted fp32
    cvt_prep_kernel<<<dim3(128, 7), blk>>>(
        target, tgt, ML * D_MODEL,
        source, src, S * D_LLM,
        value,  val, S * D_LLM,
        Wq, wq, D_MODEL * HD,
        Wk, wk, D_LLM * HD,
        Wv, wv, D_LLM * HD,
        Wo, wo, HD * D_LLM);

    // Q = target @ Wq + bq   (output tf32-formatted)
    gemm_tf32_q_kernel<<<dim3(HD / BNT, ML / BMT), blk>>>(tgt, wq, bq, qb, ML, HD, D_MODEL);
    // K,V projections fused (outputs tf32-formatted)
    gemm_tf32_dual_kernel<<<dim3(HD / BNT, (1000 + BMT - 1) / BMT, 2), blk>>>(
        src, wk, bk, kb, val, wv, bv, vb, S, HD, D_LLM);

    // fused tensor-core attention (output tf32-formatted)
    const size_t asmem = (64 * QK_PITCH + 64 * V_PITCH + QT * P_PITCH) * sizeof(uint32_t);
    cudaFuncSetAttribute(attn_tc_kernel, cudaFuncAttributeMaxDynamicSharedMemorySize, (int)asmem);
    attn_tc_kernel<<<dim3(L_DIM / QT, B_DIM * N_HEADS), blk, asmem>>>(
        qb, kb, vb, ab, alpha, beta, S);

    // out = attn @ Wo + bo   (true fp32 output)
    gemm_tf32_out_kernel<<<dim3(D_LLM / BNT, ML / BMT), blk>>>(ab, wo, bo, out, ML, D_LLM, D_MODEL);
}

// round 13
// speedup vs baseline: 1.0252x; 1.0252x over previous
#include <cuda_runtime.h>
#include <cstdint>

// ---------------------------------------------------------------------------
// Problem constants
// ---------------------------------------------------------------------------
#define B_DIM 8
#define L_DIM 1024
#define D_MODEL 1024
#define N_HEADS 16
#define D_KEYS 64
#define D_LLM 4096
#define HD 1024           // N_HEADS * D_KEYS
#define ML (B_DIM * L_DIM) // 8192

// Scratch (device globals: allocation-free contract)
__device__ float g_q[ML * HD];
__device__ float g_k[1024 * HD];
__device__ float g_v[1024 * HD];
__device__ float g_attn[ML * HD];

__device__ __forceinline__ uint32_t f32_to_tf32(float x) {
    uint32_t r;
    asm("cvt.rna.tf32.f32 %0, %1;" : "=r"(r) : "f"(x));
    return r;
}
__device__ __forceinline__ uint32_t smem_u32(const void* p) {
    uint32_t a;
    asm("{ .reg .u64 t; cvta.to.shared.u64 t, %1; cvt.u32.u64 %0, t; }" : "=r"(a) : "l"(p));
    return a;
}
__device__ __forceinline__ void cp_async16(uint32_t dst, const void* src, bool pred) {
    const int sz = pred ? 16 : 0;   // src-size 0 -> 16B zero-fill
    asm volatile("cp.async.cg.shared.global [%0], [%1], 16, %2;"
                 :: "r"(dst), "l"(src), "r"(sz) : "memory");
}
__device__ __forceinline__ void cp_async_commit() {
    asm volatile("cp.async.commit_group;" ::: "memory");
}
template <int N>
__device__ __forceinline__ void cp_async_wait() {
    asm volatile("cp.async.wait_group %0;" :: "n"(N) : "memory");
}

#define MMA_TF32(d, a, b0v, b1v)                                               \
    asm volatile(                                                              \
        "mma.sync.aligned.m16n8k8.row.col.f32.tf32.tf32.f32 "                  \
        "{%0,%1,%2,%3}, {%4,%5,%6,%7}, {%8,%9}, {%0,%1,%2,%3};"                \
        : "+f"((d)[0]), "+f"((d)[1]), "+f"((d)[2]), "+f"((d)[3])               \
        : "r"((a)[0]), "r"((a)[1]), "r"((a)[2]), "r"((a)[3]),                  \
          "r"(b0v), "r"(b1v))

// ---------------------------------------------------------------------------
// TF32 tensor-core GEMM, cp.async 4-stage pipeline (round-11 proven config):
//   C[M,N] = A[M,K] @ W[K,N] + bias[N]
// 128x128 CTA tile, BK=8, 256 threads (8 warps, 2x4), warp tile 64x32.
// SMEM holds raw fp32; tf32 cvt at fragment read (idempotent on pre-formatted
// inputs). ONE sync per k-iter. CVT_OUT: emit tf32-formatted output.
// ---------------------------------------------------------------------------
#define BMT 128
#define BNT 128
#define BKT 8
#define APITCH 12
#define BPITCH 136
#define STAGES 4

template <bool CVT_OUT>
__device__ __forceinline__
void gemm_body(const float* __restrict__ A, const float* __restrict__ W,
               const float* __restrict__ bias, float* __restrict__ C,
               int M, int N, int K)
{
    __shared__ float As[STAGES][BMT][APITCH];   // 24 KB
    __shared__ float Bs[STAGES][BKT][BPITCH];   // 17 KB

    const int tid  = threadIdx.x;
    const int lane = tid & 31;
    const int warp = tid >> 5;
    const int wm = (warp >> 2) * 64;
    const int wn = (warp & 3) * 32;
    const int grp = lane >> 2;
    const int tig = lane & 3;

    const int m0 = blockIdx.y * BMT;
    const int n0 = blockIdx.x * BNT;

    const int a_row = tid >> 1;            // 0..127
    const int a_k   = (tid & 1) << 2;      // 0 or 4
    const int b_k   = tid >> 5;            // 0..7
    const int b_n   = (tid & 31) << 2;     // 0..124

    const bool a_ok = (m0 + a_row) < M;
    const float* a_src = A + (size_t)(m0 + a_row) * K + a_k;
    const float* b_src = W + (size_t)b_k * N + n0 + b_n;

    const uint32_t a_dst0 = smem_u32(&As[0][a_row][a_k]);
    const uint32_t b_dst0 = smem_u32(&Bs[0][b_k][b_n]);
    const uint32_t a_stride = (uint32_t)(BMT * APITCH * 4);
    const uint32_t b_stride = (uint32_t)(BKT * BPITCH * 4);

    float acc[4][4][4];
    #pragma unroll
    for (int i = 0; i < 4; i++)
        #pragma unroll
        for (int j = 0; j < 4; j++)
            #pragma unroll
            for (int r = 0; r < 4; r++) acc[i][j][r] = 0.0f;

    const int nk = K / BKT;

    // ---- prologue: fill STAGES-1 stages ----
    #pragma unroll
    for (int s = 0; s < STAGES - 1; s++) {
        if (s < nk) {
            cp_async16(a_dst0 + s * a_stride, a_src + (size_t)s * BKT, a_ok);
            cp_async16(b_dst0 + s * b_stride, b_src + (size_t)s * BKT * N, true);
        }
        cp_async_commit();
    }

    for (int kt = 0; kt < nk; kt++) {
        const int cur = kt & (STAGES - 1);
        cp_async_wait<STAGES - 2>();
        __syncthreads();
        // Single barrier per iteration (proven safe in round 11).

        {
            const int kn = kt + STAGES - 1;
            if (kn < nk) {
                const int st = kn & (STAGES - 1);
                cp_async16(a_dst0 + st * a_stride, a_src + (size_t)kn * BKT, a_ok);
                cp_async16(b_dst0 + st * b_stride, b_src + (size_t)kn * BKT * N, true);
            }
            cp_async_commit();
        }

        // fragments (fp32 -> tf32 at read; idempotent on formatted data)
        uint32_t af[4][4], bf[4][2];
        #pragma unroll
        for (int tm = 0; tm < 4; tm++) {
            const int rb = wm + tm * 16 + grp;
            af[tm][0] = f32_to_tf32(As[cur][rb][tig]);
            af[tm][1] = f32_to_tf32(As[cur][rb + 8][tig]);
            af[tm][2] = f32_to_tf32(As[cur][rb][tig + 4]);
            af[tm][3] = f32_to_tf32(As[cur][rb + 8][tig + 4]);
        }
        #pragma unroll
        for (int tn = 0; tn < 4; tn++) {
            const int nb = wn + tn * 8 + grp;
            bf[tn][0] = f32_to_tf32(Bs[cur][tig][nb]);
            bf[tn][1] = f32_to_tf32(Bs[cur][tig + 4][nb]);
        }

        #pragma unroll
        for (int tm = 0; tm < 4; tm++)
            #pragma unroll
            for (int tn = 0; tn < 4; tn++)
                MMA_TF32(acc[tm][tn], af[tm], bf[tn][0], bf[tn][1]);
        // no bottom sync
    }

    // ---- epilogue: bias + store (optionally tf32-formatted) ----
    #pragma unroll
    for (int tm = 0; tm < 4; tm++) {
        const int row  = m0 + wm + tm * 16 + grp;
        const int row2 = row + 8;
        #pragma unroll
        for (int tn = 0; tn < 4; tn++) {
            const int col = n0 + wn + tn * 8 + 2 * tig;
            const float b0v = bias[col];
            const float b1v = bias[col + 1];
            float o0 = acc[tm][tn][0] + b0v, o1 = acc[tm][tn][1] + b1v;
            float o2 = acc[tm][tn][2] + b0v, o3 = acc[tm][tn][3] + b1v;
            if (CVT_OUT) {
                o0 = __uint_as_float(f32_to_tf32(o0));
                o1 = __uint_as_float(f32_to_tf32(o1));
                o2 = __uint_as_float(f32_to_tf32(o2));
                o3 = __uint_as_float(f32_to_tf32(o3));
            }
            if (row < M)  *(float2*)(C + (size_t)row * N + col)  = make_float2(o0, o1);
            if (row2 < M) *(float2*)(C + (size_t)row2 * N + col) = make_float2(o2, o3);
        }
    }
}

__global__ __launch_bounds__(256, 2)
void gemm_tf32_out_kernel(const float* __restrict__ A, const float* __restrict__ W,
                          const float* __restrict__ bias, float* __restrict__ C,
                          int M, int N, int K)
{
    gemm_body<false>(A, W, bias, C, M, N, K);
}

__global__ __launch_bounds__(256, 2)
void gemm_tf32_q_kernel(const float* __restrict__ A, const float* __restrict__ W,
                        const float* __restrict__ bias, float* __restrict__ C,
                        int M, int N, int K)
{
    gemm_body<true>(A, W, bias, C, M, N, K);
}

__global__ __launch_bounds__(256, 2)
void gemm_tf32_dual_kernel(const float* __restrict__ A0, const float* __restrict__ W0,
                           const float* __restrict__ b0, float* __restrict__ C0,
                           const float* __restrict__ A1, const float* __restrict__ W1,
                           const float* __restrict__ b1, float* __restrict__ C1,
                           int M, int N, int K)
{
    if (blockIdx.z == 0) gemm_body<true>(A0, W0, b0, C0, M, N, K);
    else                 gemm_body<true>(A1, W1, b1, C1, M, N, K);
}

// ---------------------------------------------------------------------------
// Tensor-core flash attention (tf32 m16n8k8), head_dim = 64.
// One block per (b, h, 128-query tile). 256 threads = 8 warps.
// q/k/v arrive tf32-formatted from the projection epilogues -> staging is a
// plain bit-copy (round-12 measured: 298us). Output tf32-formatted.
// ---------------------------------------------------------------------------
#define QT 128
#define QK_PITCH 68
#define V_PITCH  72
#define P_PITCH  72

__global__ __launch_bounds__(256, 2)
void attn_tc_kernel(const float* __restrict__ q, const float* __restrict__ k,
                    const float* __restrict__ v, float* __restrict__ o_out,
                    const float* __restrict__ alpha, const float* __restrict__ beta,
                    int S)
{
    extern __shared__ uint32_t smu[];
    uint32_t* Ks = smu;
    uint32_t* Vs = Ks + 64 * QK_PITCH;
    uint32_t* Ps = Vs + 64 * V_PITCH;

    const int tid  = threadIdx.x;
    const int lane = tid & 31;
    const int warp = tid >> 5;
    const int grp  = lane >> 2;
    const int tig  = lane & 3;

    const int l0 = blockIdx.x * QT;
    const int b  = blockIdx.y >> 4;
    const int h  = blockIdx.y & 15;

    const float scale = alpha[0] * beta[0] * 0.125f;

    const float* qbase = q + ((size_t)(b * L_DIM + l0)) * HD + h * D_KEYS;
    #pragma unroll
    for (int p = 0; p < 8; p++) {
        const int idx = p * 256 + tid;
        const int row = idx >> 4;
        const int e4  = (idx & 15) << 2;
        uint4 t = *(const uint4*)(qbase + (size_t)row * HD + e4);
        *(uint4*)(Ps + row * P_PITCH + e4) = t;
    }
    __syncthreads();

    uint32_t qf[8][4];
    {
        const int qrow = warp * 16 + grp;
        #pragma unroll
        for (int ks = 0; ks < 8; ks++) {
            qf[ks][0] = Ps[qrow * P_PITCH + ks * 8 + tig];
            qf[ks][1] = Ps[(qrow + 8) * P_PITCH + ks * 8 + tig];
            qf[ks][2] = Ps[qrow * P_PITCH + ks * 8 + tig + 4];
            qf[ks][3] = Ps[(qrow + 8) * P_PITCH + ks * 8 + tig + 4];
        }
    }

    float m0r = -1e30f, m1r = -1e30f, l0r = 0.0f, l1r = 0.0f;
    float oa[8][4];
    #pragma unroll
    for (int nt = 0; nt < 8; nt++)
        #pragma unroll
        for (int r = 0; r < 4; r++) oa[nt][r] = 0.0f;

    const int nTiles = (S + 63) >> 6;
    for (int ts = 0; ts < nTiles; ts++) {
        const int s0 = ts * 64;
        __syncthreads();

        const float* kb2 = k + (size_t)s0 * HD + h * D_KEYS;
        const float* vb2 = v + (size_t)s0 * HD + h * D_KEYS;
        #pragma unroll
        for (int p = 0; p < 4; p++) {
            const int idx = p * 256 + tid;
            const int j  = idx >> 4;
            const int e4 = (idx & 15) << 2;
            uint4 tk, tv;
            if (s0 + j < S) {
                tk = *(const uint4*)(kb2 + (size_t)j * HD + e4);
                tv = *(const uint4*)(vb2 + (size_t)j * HD + e4);
            } else {
                tk = make_uint4(0u, 0u, 0u, 0u);
                tv = tk;
            }
            *(uint4*)(Ks + j * QK_PITCH + e4) = tk;
            *(uint4*)(Vs + j * V_PITCH + e4) = tv;
        }
        __syncthreads();

        float sc[8][4];
        #pragma unroll
        for (int nt = 0; nt < 8; nt++)
            #pragma unroll
            for (int r = 0; r < 4; r++) sc[nt][r] = 0.0f;

        #pragma unroll
        for (int ks = 0; ks < 8; ks++) {
            #pragma unroll
            for (int nt = 0; nt < 8; nt++) {
                const uint32_t b0v = Ks[(nt * 8 + grp) * QK_PITCH + ks * 8 + tig];
                const uint32_t b1v = Ks[(nt * 8 + grp) * QK_PITCH + ks * 8 + tig + 4];
                MMA_TF32(sc[nt], qf[ks], b0v, b1v);
            }
        }

        #pragma unroll
        for (int nt = 0; nt < 8; nt++) {
            const int c0 = s0 + nt * 8 + 2 * tig;
            const bool v0 = c0 < S, v1 = (c0 + 1) < S;
            sc[nt][0] = v0 ? sc[nt][0] * scale : -1e30f;
            sc[nt][1] = v1 ? sc[nt][1] * scale : -1e30f;
            sc[nt][2] = v0 ? sc[nt][2] * scale : -1e30f;
            sc[nt][3] = v1 ? sc[nt][3] * scale : -1e30f;
        }

        float mt0 = -1e30f, mt1 = -1e30f;
        #pragma unroll
        for (int nt = 0; nt < 8; nt++) {
            mt0 = fmaxf(mt0, fmaxf(sc[nt][0], sc[nt][1]));
            mt1 = fmaxf(mt1, fmaxf(sc[nt][2], sc[nt][3]));
        }
        mt0 = fmaxf(mt0, __shfl_xor_sync(0xffffffffu, mt0, 1));
        mt0 = fmaxf(mt0, __shfl_xor_sync(0xffffffffu, mt0, 2));
        mt1 = fmaxf(mt1, __shfl_xor_sync(0xffffffffu, mt1, 1));
        mt1 = fmaxf(mt1, __shfl_xor_sync(0xffffffffu, mt1, 2));

        const float mn0 = fmaxf(m0r, mt0);
        const float mn1 = fmaxf(m1r, mt1);
        const float fac0 = __expf(m0r - mn0);
        const float fac1 = __expf(m1r - mn1);
        m0r = mn0; m1r = mn1;
        l0r *= fac0; l1r *= fac1;
        #pragma unroll
        for (int nt = 0; nt < 8; nt++) {
            oa[nt][0] *= fac0; oa[nt][1] *= fac0;
            oa[nt][2] *= fac1; oa[nt][3] *= fac1;
        }

        float rs0 = 0.0f, rs1 = 0.0f;
        #pragma unroll
        for (int nt = 0; nt < 8; nt++) {
            sc[nt][0] = __expf(sc[nt][0] - mn0);
            sc[nt][1] = __expf(sc[nt][1] - mn0);
            sc[nt][2] = __expf(sc[nt][2] - mn1);
            sc[nt][3] = __expf(sc[nt][3] - mn1);
            rs0 += sc[nt][0] + sc[nt][1];
            rs1 += sc[nt][2] + sc[nt][3];
        }
        rs0 += __shfl_xor_sync(0xffffffffu, rs0, 1);
        rs0 += __shfl_xor_sync(0xffffffffu, rs0, 2);
        rs1 += __shfl_xor_sync(0xffffffffu, rs1, 1);
        rs1 += __shfl_xor_sync(0xffffffffu, rs1, 2);
        l0r += rs0; l1r += rs1;

        {
            const int pr0 = warp * 16 + grp;
            #pragma unroll
            for (int nt = 0; nt < 8; nt++) {
                uint2 p01 = make_uint2(f32_to_tf32(sc[nt][0]), f32_to_tf32(sc[nt][1]));
                uint2 p23 = make_uint2(f32_to_tf32(sc[nt][2]), f32_to_tf32(sc[nt][3]));
                *(uint2*)&Ps[pr0 * P_PITCH + nt * 8 + 2 * tig] = p01;
                *(uint2*)&Ps[(pr0 + 8) * P_PITCH + nt * 8 + 2 * tig] = p23;
            }
        }
        __syncwarp();

        #pragma unroll
        for (int ks = 0; ks < 8; ks++) {
            uint32_t af[4];
            const int pr0 = warp * 16 + grp;
            af[0] = Ps[pr0 * P_PITCH + ks * 8 + tig];
            af[1] = Ps[(pr0 + 8) * P_PITCH + ks * 8 + tig];
            af[2] = Ps[pr0 * P_PITCH + ks * 8 + tig + 4];
            af[3] = Ps[(pr0 + 8) * P_PITCH + ks * 8 + tig + 4];
            #pragma unroll
            for (int nt = 0; nt < 8; nt++) {
                const uint32_t b0v = Vs[(ks * 8 + tig) * V_PITCH + nt * 8 + grp];
                const uint32_t b1v = Vs[(ks * 8 + tig + 4) * V_PITCH + nt * 8 + grp];
                MMA_TF32(oa[nt], af, b0v, b1v);
            }
        }
    }

    // normalize + store, tf32-formatted for the O-projection
    const float inv0 = 1.0f / l0r;
    const float inv1 = 1.0f / l1r;
    float* ob = o_out + ((size_t)(b * L_DIM + l0 + warp * 16 + grp)) * HD + h * D_KEYS;
    #pragma unroll
    for (int nt = 0; nt < 8; nt++) {
        const int col = nt * 8 + 2 * tig;
        uint2 o0 = make_uint2(f32_to_tf32(oa[nt][0] * inv0), f32_to_tf32(oa[nt][1] * inv0));
        uint2 o1 = make_uint2(f32_to_tf32(oa[nt][2] * inv1), f32_to_tf32(oa[nt][3] * inv1));
        *(uint2*)(ob + col) = o0;
        *(uint2*)(ob + (size_t)8 * HD + col) = o1;
    }
}

// ---------------------------------------------------------------------------
// Launch
// ---------------------------------------------------------------------------
extern "C" void kernel_launch(void* const* d_in, const int* in_sizes, int n_in,
                              void* d_out, int out_size)
{
    const float* target = (const float*)d_in[0];
    const float* source = (const float*)d_in[1];
    const float* value  = (const float*)d_in[2];
    const float* Wq = (const float*)d_in[3];
    const float* bq = (const float*)d_in[4];
    const float* Wk = (const float*)d_in[5];
    const float* bk = (const float*)d_in[6];
    const float* Wv = (const float*)d_in[7];
    const float* bv = (const float*)d_in[8];
    const float* Wo = (const float*)d_in[9];
    const float* bo = (const float*)d_in[10];
    const float* alpha = (const float*)d_in[11];
    const float* beta  = (const float*)d_in[12];
    float* out = (float*)d_out;

    const int S = in_sizes[1] / D_LLM;   // 1000

    float *qb, *kb, *vb, *ab;
    cudaGetSymbolAddress((void**)&qb, g_q);
    cudaGetSymbolAddress((void**)&kb, g_k);
    cudaGetSymbolAddress((void**)&vb, g_v);
    cudaGetSymbolAddress((void**)&ab, g_attn);

    dim3 blk(256);

    // Q = target @ Wq + bq   (output tf32-formatted)
    gemm_tf32_q_kernel<<<dim3(HD / BNT, ML / BMT), blk>>>(target, Wq, bq, qb, ML, HD, D_MODEL);
    // K,V projections fused (outputs tf32-formatted)
    gemm_tf32_dual_kernel<<<dim3(HD / BNT, (1000 + BMT - 1) / BMT, 2), blk>>>(
        source, Wk, bk, kb, value, Wv, bv, vb, S, HD, D_LLM);

    // fused tensor-core attention (bit-copy staging; output tf32-formatted)
    const size_t asmem = (64 * QK_PITCH + 64 * V_PITCH + QT * P_PITCH) * sizeof(uint32_t);
    cudaFuncSetAttribute(attn_tc_kernel, cudaFuncAttributeMaxDynamicSharedMemorySize, (int)asmem);
    attn_tc_kernel<<<dim3(L_DIM / QT, B_DIM * N_HEADS), blk, asmem>>>(
        qb, kb, vb, ab, alpha, beta, S);

    // out = attn @ Wo + bo   (true fp32 output)
    gemm_tf32_out_kernel<<<dim3(D_LLM / BNT, ML / BMT), blk>>>(ab, Wo, bo, out, ML, D_LLM, D_MODEL);
}

// round 14
// speedup vs baseline: 1.0633x; 1.0371x over previous
#include <cuda_runtime.h>
#include <cstdint>

// ---------------------------------------------------------------------------
// Problem constants
// ---------------------------------------------------------------------------
#define B_DIM 8
#define L_DIM 1024
#define D_MODEL 1024
#define N_HEADS 16
#define D_KEYS 64
#define D_LLM 4096
#define HD 1024           // N_HEADS * D_KEYS
#define ML (B_DIM * L_DIM) // 8192
#define KV_SEG 2048       // split-K segment for K/V projections

// Scratch (device globals: allocation-free contract)
__device__ float g_q[ML * HD];
__device__ float g_k[1024 * HD];
__device__ float g_v[1024 * HD];
__device__ float g_attn[ML * HD];
__device__ float g_kpart[2 * 1024 * HD];   // split-K partials (K proj)
__device__ float g_vpart[2 * 1024 * HD];   // split-K partials (V proj)

__device__ __forceinline__ uint32_t f32_to_tf32(float x) {
    uint32_t r;
    asm("cvt.rna.tf32.f32 %0, %1;" : "=r"(r) : "f"(x));
    return r;
}
__device__ __forceinline__ uint32_t smem_u32(const void* p) {
    uint32_t a;
    asm("{ .reg .u64 t; cvta.to.shared.u64 t, %1; cvt.u32.u64 %0, t; }" : "=r"(a) : "l"(p));
    return a;
}
__device__ __forceinline__ void cp_async16(uint32_t dst, const void* src, bool pred) {
    const int sz = pred ? 16 : 0;   // src-size 0 -> 16B zero-fill
    asm volatile("cp.async.cg.shared.global [%0], [%1], 16, %2;"
                 :: "r"(dst), "l"(src), "r"(sz) : "memory");
}
__device__ __forceinline__ void cp_async_commit() {
    asm volatile("cp.async.commit_group;" ::: "memory");
}
template <int N>
__device__ __forceinline__ void cp_async_wait() {
    asm volatile("cp.async.wait_group %0;" :: "n"(N) : "memory");
}

#define MMA_TF32(d, a, b0v, b1v)                                               \
    asm volatile(                                                              \
        "mma.sync.aligned.m16n8k8.row.col.f32.tf32.tf32.f32 "                  \
        "{%0,%1,%2,%3}, {%4,%5,%6,%7}, {%8,%9}, {%0,%1,%2,%3};"                \
        : "+f"((d)[0]), "+f"((d)[1]), "+f"((d)[2]), "+f"((d)[3])               \
        : "r"((a)[0]), "r"((a)[1]), "r"((a)[2]), "r"((a)[3]),                  \
          "r"(b0v), "r"(b1v))

// ---------------------------------------------------------------------------
// TF32 tensor-core GEMM, cp.async 4-stage pipeline (round-11 proven config):
//   C[M,N] = A[M,K(lda)] @ W[K,N] (+ bias[N] if ADD_BIAS)
// 128x128 CTA tile, BK=8, 256 threads (8 warps, 2x4), warp tile 64x32.
// SMEM raw fp32; tf32 cvt at fragment read. ONE sync per k-iter.
// CVT_OUT: emit tf32-formatted output.
// ---------------------------------------------------------------------------
#define BMT 128
#define BNT 128
#define BKT 8
#define APITCH 12
#define BPITCH 136
#define STAGES 4

template <bool CVT_OUT, bool ADD_BIAS>
__device__ __forceinline__
void gemm_body(const float* __restrict__ A, const float* __restrict__ W,
               const float* __restrict__ bias, float* __restrict__ C,
               int M, int N, int K, int lda)
{
    __shared__ float As[STAGES][BMT][APITCH];   // 24 KB
    __shared__ float Bs[STAGES][BKT][BPITCH];   // 17 KB

    const int tid  = threadIdx.x;
    const int lane = tid & 31;
    const int warp = tid >> 5;
    const int wm = (warp >> 2) * 64;
    const int wn = (warp & 3) * 32;
    const int grp = lane >> 2;
    const int tig = lane & 3;

    const int m0 = blockIdx.y * BMT;
    const int n0 = blockIdx.x * BNT;

    const int a_row = tid >> 1;            // 0..127
    const int a_k   = (tid & 1) << 2;      // 0 or 4
    const int b_k   = tid >> 5;            // 0..7
    const int b_n   = (tid & 31) << 2;     // 0..124

    const bool a_ok = (m0 + a_row) < M;
    const float* a_src = A + (size_t)(m0 + a_row) * lda + a_k;
    const float* b_src = W + (size_t)b_k * N + n0 + b_n;

    const uint32_t a_dst0 = smem_u32(&As[0][a_row][a_k]);
    const uint32_t b_dst0 = smem_u32(&Bs[0][b_k][b_n]);
    const uint32_t a_stride = (uint32_t)(BMT * APITCH * 4);
    const uint32_t b_stride = (uint32_t)(BKT * BPITCH * 4);

    float acc[4][4][4];
    #pragma unroll
    for (int i = 0; i < 4; i++)
        #pragma unroll
        for (int j = 0; j < 4; j++)
            #pragma unroll
            for (int r = 0; r < 4; r++) acc[i][j][r] = 0.0f;

    const int nk = K / BKT;

    // ---- prologue: fill STAGES-1 stages ----
    #pragma unroll
    for (int s = 0; s < STAGES - 1; s++) {
        if (s < nk) {
            cp_async16(a_dst0 + s * a_stride, a_src + (size_t)s * BKT, a_ok);
            cp_async16(b_dst0 + s * b_stride, b_src + (size_t)s * BKT * N, true);
        }
        cp_async_commit();
    }

    for (int kt = 0; kt < nk; kt++) {
        const int cur = kt & (STAGES - 1);
        cp_async_wait<STAGES - 2>();
        __syncthreads();
        // Single barrier per iteration (proven safe in round 11).

        {
            const int kn = kt + STAGES - 1;
            if (kn < nk) {
                const int st = kn & (STAGES - 1);
                cp_async16(a_dst0 + st * a_stride, a_src + (size_t)kn * BKT, a_ok);
                cp_async16(b_dst0 + st * b_stride, b_src + (size_t)kn * BKT * N, true);
            }
            cp_async_commit();
        }

        // fragments (fp32 -> tf32 at read; idempotent on formatted data)
        uint32_t af[4][4], bf[4][2];
        #pragma unroll
        for (int tm = 0; tm < 4; tm++) {
            const int rb = wm + tm * 16 + grp;
            af[tm][0] = f32_to_tf32(As[cur][rb][tig]);
            af[tm][1] = f32_to_tf32(As[cur][rb + 8][tig]);
            af[tm][2] = f32_to_tf32(As[cur][rb][tig + 4]);
            af[tm][3] = f32_to_tf32(As[cur][rb + 8][tig + 4]);
        }
        #pragma unroll
        for (int tn = 0; tn < 4; tn++) {
            const int nb = wn + tn * 8 + grp;
            bf[tn][0] = f32_to_tf32(Bs[cur][tig][nb]);
            bf[tn][1] = f32_to_tf32(Bs[cur][tig + 4][nb]);
        }

        #pragma unroll
        for (int tm = 0; tm < 4; tm++)
            #pragma unroll
            for (int tn = 0; tn < 4; tn++)
                MMA_TF32(acc[tm][tn], af[tm], bf[tn][0], bf[tn][1]);
        // no bottom sync
    }

    // ---- epilogue ----
    #pragma unroll
    for (int tm = 0; tm < 4; tm++) {
        const int row  = m0 + wm + tm * 16 + grp;
        const int row2 = row + 8;
        #pragma unroll
        for (int tn = 0; tn < 4; tn++) {
            const int col = n0 + wn + tn * 8 + 2 * tig;
            float b0v = 0.0f, b1v = 0.0f;
            if (ADD_BIAS) { b0v = bias[col]; b1v = bias[col + 1]; }
            float o0 = acc[tm][tn][0] + b0v, o1 = acc[tm][tn][1] + b1v;
            float o2 = acc[tm][tn][2] + b0v, o3 = acc[tm][tn][3] + b1v;
            if (CVT_OUT) {
                o0 = __uint_as_float(f32_to_tf32(o0));
                o1 = __uint_as_float(f32_to_tf32(o1));
                o2 = __uint_as_float(f32_to_tf32(o2));
                o3 = __uint_as_float(f32_to_tf32(o3));
            }
            if (row < M)  *(float2*)(C + (size_t)row * N + col)  = make_float2(o0, o1);
            if (row2 < M) *(float2*)(C + (size_t)row2 * N + col) = make_float2(o2, o3);
        }
    }
}

__global__ __launch_bounds__(256, 2)
void gemm_tf32_out_kernel(const float* __restrict__ A, const float* __restrict__ W,
                          const float* __restrict__ bias, float* __restrict__ C,
                          int M, int N, int K)
{
    gemm_body<false, true>(A, W, bias, C, M, N, K, K);
}

__global__ __launch_bounds__(256, 2)
void gemm_tf32_q_kernel(const float* __restrict__ A, const float* __restrict__ W,
                        const float* __restrict__ bias, float* __restrict__ C,
                        int M, int N, int K)
{
    gemm_body<true, true>(A, W, bias, C, M, N, K, K);
}

// K/V projections, split-K x2. grid = (8, 8, 4):
//   z&1 selects K vs V; z>>1 selects k-segment. Partials, no bias, raw fp32.
__global__ __launch_bounds__(256, 2)
void gemm_kv_split_kernel(const float* __restrict__ src, const float* __restrict__ Wk,
                          float* __restrict__ kpart,
                          const float* __restrict__ val, const float* __restrict__ Wv,
                          float* __restrict__ vpart,
                          int S)
{
    const int z = blockIdx.z;
    const int op  = z & 1;
    const int seg = z >> 1;
    const float* A = (op ? val : src) + (size_t)seg * KV_SEG;
    const float* W = (op ? Wv : Wk) + (size_t)seg * KV_SEG * HD;
    float* C = (op ? vpart : kpart) + (size_t)seg * 1024 * HD;
    gemm_body<false, false>(A, W, nullptr, C, S, HD, KV_SEG, D_LLM);
}

// combine split-K partials: out = tf32(part0 + part1 + bias)
__global__ __launch_bounds__(256)
void kv_combine_kernel(const float* __restrict__ kpart, const float* __restrict__ bk,
                       float* __restrict__ kout,
                       const float* __restrict__ vpart, const float* __restrict__ bv,
                       float* __restrict__ vout, int n)
{
    const int n4 = n >> 2;
    const int stride = gridDim.x * blockDim.x;
    const size_t off = (size_t)1024 * HD;
    for (int i = blockIdx.x * blockDim.x + threadIdx.x; i < n4; i += stride) {
        const int col4 = (i << 2) & (HD - 1);
        float4 kb = *(const float4*)(bk + col4);
        float4 vb = *(const float4*)(bv + col4);
        float4 k0 = ((const float4*)kpart)[i];
        float4 k1 = ((const float4*)(kpart + off))[i];
        float4 v0 = ((const float4*)vpart)[i];
        float4 v1 = ((const float4*)(vpart + off))[i];
        uint4 ko, vo;
        ko.x = f32_to_tf32(k0.x + k1.x + kb.x);
        ko.y = f32_to_tf32(k0.y + k1.y + kb.y);
        ko.z = f32_to_tf32(k0.z + k1.z + kb.z);
        ko.w = f32_to_tf32(k0.w + k1.w + kb.w);
        vo.x = f32_to_tf32(v0.x + v1.x + vb.x);
        vo.y = f32_to_tf32(v0.y + v1.y + vb.y);
        vo.z = f32_to_tf32(v0.z + v1.z + vb.z);
        vo.w = f32_to_tf32(v0.w + v1.w + vb.w);
        ((uint4*)kout)[i] = ko;
        ((uint4*)vout)[i] = vo;
    }
}

// ---------------------------------------------------------------------------
// Tensor-core flash attention (tf32 m16n8k8), head_dim = 64.
// One block per (b, h, 128-query tile). 256 threads = 8 warps.
// q/k/v arrive tf32-formatted -> staging is a plain bit-copy (298us proven).
// Output tf32-formatted for the O-projection.
// ---------------------------------------------------------------------------
#define QT 128
#define QK_PITCH 68
#define V_PITCH  72
#define P_PITCH  72

__global__ __launch_bounds__(256, 2)
void attn_tc_kernel(const float* __restrict__ q, const float* __restrict__ k,
                    const float* __restrict__ v, float* __restrict__ o_out,
                    const float* __restrict__ alpha, const float* __restrict__ beta,
                    int S)
{
    extern __shared__ uint32_t smu[];
    uint32_t* Ks = smu;
    uint32_t* Vs = Ks + 64 * QK_PITCH;
    uint32_t* Ps = Vs + 64 * V_PITCH;

    const int tid  = threadIdx.x;
    const int lane = tid & 31;
    const int warp = tid >> 5;
    const int grp  = lane >> 2;
    const int tig  = lane & 3;

    const int l0 = blockIdx.x * QT;
    const int b  = blockIdx.y >> 4;
    const int h  = blockIdx.y & 15;

    const float scale = alpha[0] * beta[0] * 0.125f;

    const float* qbase = q + ((size_t)(b * L_DIM + l0)) * HD + h * D_KEYS;
    #pragma unroll
    for (int p = 0; p < 8; p++) {
        const int idx = p * 256 + tid;
        const int row = idx >> 4;
        const int e4  = (idx & 15) << 2;
        uint4 t = *(const uint4*)(qbase + (size_t)row * HD + e4);
        *(uint4*)(Ps + row * P_PITCH + e4) = t;
    }
    __syncthreads();

    uint32_t qf[8][4];
    {
        const int qrow = warp * 16 + grp;
        #pragma unroll
        for (int ks = 0; ks < 8; ks++) {
            qf[ks][0] = Ps[qrow * P_PITCH + ks * 8 + tig];
            qf[ks][1] = Ps[(qrow + 8) * P_PITCH + ks * 8 + tig];
            qf[ks][2] = Ps[qrow * P_PITCH + ks * 8 + tig + 4];
            qf[ks][3] = Ps[(qrow + 8) * P_PITCH + ks * 8 + tig + 4];
        }
    }

    float m0r = -1e30f, m1r = -1e30f, l0r = 0.0f, l1r = 0.0f;
    float oa[8][4];
    #pragma unroll
    for (int nt = 0; nt < 8; nt++)
        #pragma unroll
        for (int r = 0; r < 4; r++) oa[nt][r] = 0.0f;

    const int nTiles = (S + 63) >> 6;
    for (int ts = 0; ts < nTiles; ts++) {
        const int s0 = ts * 64;
        __syncthreads();

        const float* kb2 = k + (size_t)s0 * HD + h * D_KEYS;
        const float* vb2 = v + (size_t)s0 * HD + h * D_KEYS;
        #pragma unroll
        for (int p = 0; p < 4; p++) {
            const int idx = p * 256 + tid;
            const int j  = idx >> 4;
            const int e4 = (idx & 15) << 2;
            uint4 tk, tv;
            if (s0 + j < S) {
                tk = *(const uint4*)(kb2 + (size_t)j * HD + e4);
                tv = *(const uint4*)(vb2 + (size_t)j * HD + e4);
            } else {
                tk = make_uint4(0u, 0u, 0u, 0u);
                tv = tk;
            }
            *(uint4*)(Ks + j * QK_PITCH + e4) = tk;
            *(uint4*)(Vs + j * V_PITCH + e4) = tv;
        }
        __syncthreads();

        float sc[8][4];
        #pragma unroll
        for (int nt = 0; nt < 8; nt++)
            #pragma unroll
            for (int r = 0; r < 4; r++) sc[nt][r] = 0.0f;

        #pragma unroll
        for (int ks = 0; ks < 8; ks++) {
            #pragma unroll
            for (int nt = 0; nt < 8; nt++) {
                const uint32_t b0v = Ks[(nt * 8 + grp) * QK_PITCH + ks * 8 + tig];
                const uint32_t b1v = Ks[(nt * 8 + grp) * QK_PITCH + ks * 8 + tig + 4];
                MMA_TF32(sc[nt], qf[ks], b0v, b1v);
            }
        }

        #pragma unroll
        for (int nt = 0; nt < 8; nt++) {
            const int c0 = s0 + nt * 8 + 2 * tig;
            const bool v0 = c0 < S, v1 = (c0 + 1) < S;
            sc[nt][0] = v0 ? sc[nt][0] * scale : -1e30f;
            sc[nt][1] = v1 ? sc[nt][1] * scale : -1e30f;
            sc[nt][2] = v0 ? sc[nt][2] * scale : -1e30f;
            sc[nt][3] = v1 ? sc[nt][3] * scale : -1e30f;
        }

        float mt0 = -1e30f, mt1 = -1e30f;
        #pragma unroll
        for (int nt = 0; nt < 8; nt++) {
            mt0 = fmaxf(mt0, fmaxf(sc[nt][0], sc[nt][1]));
            mt1 = fmaxf(mt1, fmaxf(sc[nt][2], sc[nt][3]));
        }
        mt0 = fmaxf(mt0, __shfl_xor_sync(0xffffffffu, mt0, 1));
        mt0 = fmaxf(mt0, __shfl_xor_sync(0xffffffffu, mt0, 2));
        mt1 = fmaxf(mt1, __shfl_xor_sync(0xffffffffu, mt1, 1));
        mt1 = fmaxf(mt1, __shfl_xor_sync(0xffffffffu, mt1, 2));

        const float mn0 = fmaxf(m0r, mt0);
        const float mn1 = fmaxf(m1r, mt1);
        const float fac0 = __expf(m0r - mn0);
        const float fac1 = __expf(m1r - mn1);
        m0r = mn0; m1r = mn1;
        l0r *= fac0; l1r *= fac1;
        #pragma unroll
        for (int nt = 0; nt < 8; nt++) {
            oa[nt][0] *= fac0; oa[nt][1] *= fac0;
            oa[nt][2] *= fac1; oa[nt][3] *= fac1;
        }

        float rs0 = 0.0f, rs1 = 0.0f;
        #pragma unroll
        for (int nt = 0; nt < 8; nt++) {
            sc[nt][0] = __expf(sc[nt][0] - mn0);
            sc[nt][1] = __expf(sc[nt][1] - mn0);
            sc[nt][2] = __expf(sc[nt][2] - mn1);
            sc[nt][3] = __expf(sc[nt][3] - mn1);
            rs0 += sc[nt][0] + sc[nt][1];
            rs1 += sc[nt][2] + sc[nt][3];
        }
        rs0 += __shfl_xor_sync(0xffffffffu, rs0, 1);
        rs0 += __shfl_xor_sync(0xffffffffu, rs0, 2);
        rs1 += __shfl_xor_sync(0xffffffffu, rs1, 1);
        rs1 += __shfl_xor_sync(0xffffffffu, rs1, 2);
        l0r += rs0; l1r += rs1;

        {
            const int pr0 = warp * 16 + grp;
            #pragma unroll
            for (int nt = 0; nt < 8; nt++) {
                uint2 p01 = make_uint2(f32_to_tf32(sc[nt][0]), f32_to_tf32(sc[nt][1]));
                uint2 p23 = make_uint2(f32_to_tf32(sc[nt][2]), f32_to_tf32(sc[nt][3]));
                *(uint2*)&Ps[pr0 * P_PITCH + nt * 8 + 2 * tig] = p01;
                *(uint2*)&Ps[(pr0 + 8) * P_PITCH + nt * 8 + 2 * tig] = p23;
            }
        }
        __syncwarp();

        #pragma unroll
        for (int ks = 0; ks < 8; ks++) {
            uint32_t af[4];
            const int pr0 = warp * 16 + grp;
            af[0] = Ps[pr0 * P_PITCH + ks * 8 + tig];
            af[1] = Ps[(pr0 + 8) * P_PITCH + ks * 8 + tig];
            af[2] = Ps[pr0 * P_PITCH + ks * 8 + tig + 4];
            af[3] = Ps[(pr0 + 8) * P_PITCH + ks * 8 + tig + 4];
            #pragma unroll
            for (int nt = 0; nt < 8; nt++) {
                const uint32_t b0v = Vs[(ks * 8 + tig) * V_PITCH + nt * 8 + grp];
                const uint32_t b1v = Vs[(ks * 8 + tig + 4) * V_PITCH + nt * 8 + grp];
                MMA_TF32(oa[nt], af, b0v, b1v);
            }
        }
    }

    // normalize + store, tf32-formatted for the O-projection
    const float inv0 = 1.0f / l0r;
    const float inv1 = 1.0f / l1r;
    float* ob = o_out + ((size_t)(b * L_DIM + l0 + warp * 16 + grp)) * HD + h * D_KEYS;
    #pragma unroll
    for (int nt = 0; nt < 8; nt++) {
        const int col = nt * 8 + 2 * tig;
        uint2 o0 = make_uint2(f32_to_tf32(oa[nt][0] * inv0), f32_to_tf32(oa[nt][1] * inv0));
        uint2 o1 = make_uint2(f32_to_tf32(oa[nt][2] * inv1), f32_to_tf32(oa[nt][3] * inv1));
        *(uint2*)(ob + col) = o0;
        *(uint2*)(ob + (size_t)8 * HD + col) = o1;
    }
}

// ---------------------------------------------------------------------------
// Launch
// ---------------------------------------------------------------------------
extern "C" void kernel_launch(void* const* d_in, const int* in_sizes, int n_in,
                              void* d_out, int out_size)
{
    const float* target = (const float*)d_in[0];
    const float* source = (const float*)d_in[1];
    const float* value  = (const float*)d_in[2];
    const float* Wq = (const float*)d_in[3];
    const float* bq = (const float*)d_in[4];
    const float* Wk = (const float*)d_in[5];
    const float* bk = (const float*)d_in[6];
    const float* Wv = (const float*)d_in[7];
    const float* bv = (const float*)d_in[8];
    const float* Wo = (const float*)d_in[9];
    const float* bo = (const float*)d_in[10];
    const float* alpha = (const float*)d_in[11];
    const float* beta  = (const float*)d_in[12];
    float* out = (float*)d_out;

    const int S = in_sizes[1] / D_LLM;   // 1000

    float *qb, *kb, *vb, *ab, *kpart, *vpart;
    cudaGetSymbolAddress((void**)&qb, g_q);
    cudaGetSymbolAddress((void**)&kb, g_k);
    cudaGetSymbolAddress((void**)&vb, g_v);
    cudaGetSymbolAddress((void**)&ab, g_attn);
    cudaGetSymbolAddress((void**)&kpart, g_kpart);
    cudaGetSymbolAddress((void**)&vpart, g_vpart);

    dim3 blk(256);

    // Q = target @ Wq + bq   (output tf32-formatted)
    gemm_tf32_q_kernel<<<dim3(HD / BNT, ML / BMT), blk>>>(target, Wq, bq, qb, ML, HD, D_MODEL);

    // K,V projections: split-K x2 across 256 CTAs (one full wave)
    gemm_kv_split_kernel<<<dim3(HD / BNT, (1000 + BMT - 1) / BMT, 4), blk>>>(
        source, Wk, kpart, value, Wv, vpart, S);
    // combine partials + bias -> tf32-formatted K/V
    kv_combine_kernel<<<dim3(256), blk>>>(kpart, bk, kb, vpart, bv, vb, S * HD);

    // fused tensor-core attention (bit-copy staging; output tf32-formatted)
    const size_t asmem = (64 * QK_PITCH + 64 * V_PITCH + QT * P_PITCH) * sizeof(uint32_t);
    cudaFuncSetAttribute(attn_tc_kernel, cudaFuncAttributeMaxDynamicSharedMemorySize, (int)asmem);
    attn_tc_kernel<<<dim3(L_DIM / QT, B_DIM * N_HEADS), blk, asmem>>>(
        qb, kb, vb, ab, alpha, beta, S);

    // out = attn @ Wo + bo   (true fp32 output)
    gemm_tf32_out_kernel<<<dim3(D_LLM / BNT, ML / BMT), blk>>>(ab, Wo, bo, out, ML, D_LLM, D_MODEL);
}

// round 15
// speedup vs baseline: 1.0966x; 1.0313x over previous
#include <cuda_runtime.h>
#include <cstdint>

// ---------------------------------------------------------------------------
// Problem constants
// ---------------------------------------------------------------------------
#define B_DIM 8
#define L_DIM 1024
#define D_MODEL 1024
#define N_HEADS 16
#define D_KEYS 64
#define D_LLM 4096
#define HD 1024           // N_HEADS * D_KEYS
#define ML (B_DIM * L_DIM) // 8192
#define KV_SEG 2048       // split-K segment for K/V projections

// Scratch (device globals: allocation-free contract)
__device__ float g_q[ML * HD];
__device__ float g_k[1024 * HD];
__device__ float g_v[1024 * HD];
__device__ float g_attn[ML * HD];
__device__ float g_kpart[2 * 1024 * HD];   // split-K partials (K proj)
__device__ float g_vpart[2 * 1024 * HD];   // split-K partials (V proj)

__device__ __forceinline__ uint32_t f32_to_tf32(float x) {
    uint32_t r;
    asm("cvt.rna.tf32.f32 %0, %1;" : "=r"(r) : "f"(x));
    return r;
}
__device__ __forceinline__ uint32_t smem_u32(const void* p) {
    uint32_t a;
    asm("{ .reg .u64 t; cvta.to.shared.u64 t, %1; cvt.u32.u64 %0, t; }" : "=r"(a) : "l"(p));
    return a;
}
__device__ __forceinline__ void cp_async16(uint32_t dst, const void* src, bool pred) {
    const int sz = pred ? 16 : 0;   // src-size 0 -> 16B zero-fill
    asm volatile("cp.async.cg.shared.global [%0], [%1], 16, %2;"
                 :: "r"(dst), "l"(src), "r"(sz) : "memory");
}
__device__ __forceinline__ void cp_async_commit() {
    asm volatile("cp.async.commit_group;" ::: "memory");
}
template <int N>
__device__ __forceinline__ void cp_async_wait() {
    asm volatile("cp.async.wait_group %0;" :: "n"(N) : "memory");
}

#define MMA_TF32(d, a, b0v, b1v)                                               \
    asm volatile(                                                              \
        "mma.sync.aligned.m16n8k8.row.col.f32.tf32.tf32.f32 "                  \
        "{%0,%1,%2,%3}, {%4,%5,%6,%7}, {%8,%9}, {%0,%1,%2,%3};"                \
        : "+f"((d)[0]), "+f"((d)[1]), "+f"((d)[2]), "+f"((d)[3])               \
        : "r"((a)[0]), "r"((a)[1]), "r"((a)[2]), "r"((a)[3]),                  \
          "r"(b0v), "r"(b1v))

// ---------------------------------------------------------------------------
// TF32 tensor-core GEMM, cp.async 4-stage pipeline (proven config):
//   C[M,N] = A[M,K(lda)] @ W[K,N] (+ bias[N] if ADD_BIAS)
// 128x128 CTA tile, BK=8, 256 threads (8 warps, 2x4), warp tile 64x32.
// SMEM raw fp32; tf32 cvt at fragment read. ONE sync per k-iter.
// CVT_OUT: emit tf32-formatted output.
// ---------------------------------------------------------------------------
#define BMT 128
#define BNT 128
#define BKT 8
#define APITCH 12
#define BPITCH 136
#define STAGES 4

template <bool CVT_OUT, bool ADD_BIAS>
__device__ __forceinline__
void gemm_body(const float* __restrict__ A, const float* __restrict__ W,
               const float* __restrict__ bias, float* __restrict__ C,
               int M, int N, int K, int lda, int bx, int by)
{
    __shared__ float As[STAGES][BMT][APITCH];   // 24 KB
    __shared__ float Bs[STAGES][BKT][BPITCH];   // 17 KB

    const int tid  = threadIdx.x;
    const int lane = tid & 31;
    const int warp = tid >> 5;
    const int wm = (warp >> 2) * 64;
    const int wn = (warp & 3) * 32;
    const int grp = lane >> 2;
    const int tig = lane & 3;

    const int m0 = by * BMT;
    const int n0 = bx * BNT;

    const int a_row = tid >> 1;            // 0..127
    const int a_k   = (tid & 1) << 2;      // 0 or 4
    const int b_k   = tid >> 5;            // 0..7
    const int b_n   = (tid & 31) << 2;     // 0..124

    const bool a_ok = (m0 + a_row) < M;
    const float* a_src = A + (size_t)(m0 + a_row) * lda + a_k;
    const float* b_src = W + (size_t)b_k * N + n0 + b_n;

    const uint32_t a_dst0 = smem_u32(&As[0][a_row][a_k]);
    const uint32_t b_dst0 = smem_u32(&Bs[0][b_k][b_n]);
    const uint32_t a_stride = (uint32_t)(BMT * APITCH * 4);
    const uint32_t b_stride = (uint32_t)(BKT * BPITCH * 4);

    float acc[4][4][4];
    #pragma unroll
    for (int i = 0; i < 4; i++)
        #pragma unroll
        for (int j = 0; j < 4; j++)
            #pragma unroll
            for (int r = 0; r < 4; r++) acc[i][j][r] = 0.0f;

    const int nk = K / BKT;

    // ---- prologue: fill STAGES-1 stages ----
    #pragma unroll
    for (int s = 0; s < STAGES - 1; s++) {
        if (s < nk) {
            cp_async16(a_dst0 + s * a_stride, a_src + (size_t)s * BKT, a_ok);
            cp_async16(b_dst0 + s * b_stride, b_src + (size_t)s * BKT * N, true);
        }
        cp_async_commit();
    }

    for (int kt = 0; kt < nk; kt++) {
        const int cur = kt & (STAGES - 1);
        cp_async_wait<STAGES - 2>();
        __syncthreads();
        // Single barrier per iteration (proven safe in round 11).

        {
            const int kn = kt + STAGES - 1;
            if (kn < nk) {
                const int st = kn & (STAGES - 1);
                cp_async16(a_dst0 + st * a_stride, a_src + (size_t)kn * BKT, a_ok);
                cp_async16(b_dst0 + st * b_stride, b_src + (size_t)kn * BKT * N, true);
            }
            cp_async_commit();
        }

        // fragments (fp32 -> tf32 at read; idempotent on formatted data)
        uint32_t af[4][4], bf[4][2];
        #pragma unroll
        for (int tm = 0; tm < 4; tm++) {
            const int rb = wm + tm * 16 + grp;
            af[tm][0] = f32_to_tf32(As[cur][rb][tig]);
            af[tm][1] = f32_to_tf32(As[cur][rb + 8][tig]);
            af[tm][2] = f32_to_tf32(As[cur][rb][tig + 4]);
            af[tm][3] = f32_to_tf32(As[cur][rb + 8][tig + 4]);
        }
        #pragma unroll
        for (int tn = 0; tn < 4; tn++) {
            const int nb = wn + tn * 8 + grp;
            bf[tn][0] = f32_to_tf32(Bs[cur][tig][nb]);
            bf[tn][1] = f32_to_tf32(Bs[cur][tig + 4][nb]);
        }

        #pragma unroll
        for (int tm = 0; tm < 4; tm++)
            #pragma unroll
            for (int tn = 0; tn < 4; tn++)
                MMA_TF32(acc[tm][tn], af[tm], bf[tn][0], bf[tn][1]);
        // no bottom sync
    }

    // ---- epilogue ----
    #pragma unroll
    for (int tm = 0; tm < 4; tm++) {
        const int row  = m0 + wm + tm * 16 + grp;
        const int row2 = row + 8;
        #pragma unroll
        for (int tn = 0; tn < 4; tn++) {
            const int col = n0 + wn + tn * 8 + 2 * tig;
            float b0v = 0.0f, b1v = 0.0f;
            if (ADD_BIAS) { b0v = bias[col]; b1v = bias[col + 1]; }
            float o0 = acc[tm][tn][0] + b0v, o1 = acc[tm][tn][1] + b1v;
            float o2 = acc[tm][tn][2] + b0v, o3 = acc[tm][tn][3] + b1v;
            if (CVT_OUT) {
                o0 = __uint_as_float(f32_to_tf32(o0));
                o1 = __uint_as_float(f32_to_tf32(o1));
                o2 = __uint_as_float(f32_to_tf32(o2));
                o3 = __uint_as_float(f32_to_tf32(o3));
            }
            if (row < M)  *(float2*)(C + (size_t)row * N + col)  = make_float2(o0, o1);
            if (row2 < M) *(float2*)(C + (size_t)row2 * N + col) = make_float2(o2, o3);
        }
    }
}

__global__ __launch_bounds__(256, 2)
void gemm_tf32_out_kernel(const float* __restrict__ A, const float* __restrict__ W,
                          const float* __restrict__ bias, float* __restrict__ C,
                          int M, int N, int K)
{
    gemm_body<false, true>(A, W, bias, C, M, N, K, K, blockIdx.x, blockIdx.y);
}

// Merged Q-projection + split-K K/V projections. grid = (8, 96):
//   y in [0,32): KV split (long-running, fronted for scheduling):
//       t = y; op = (t>>3)&1 (0=K,1=V); seg = t>>4; m-tile = t&7
//   y in [32,96): Q proj, m-tile = y-32
__global__ __launch_bounds__(256, 2)
void gemm_qkv_kernel(const float* __restrict__ tgt, const float* __restrict__ Wq,
                     const float* __restrict__ bq, float* __restrict__ Cq,
                     const float* __restrict__ src, const float* __restrict__ Wk,
                     float* __restrict__ kpart,
                     const float* __restrict__ val, const float* __restrict__ Wv,
                     float* __restrict__ vpart,
                     int S)
{
    const int y = blockIdx.y;
    if (y < 32) {
        const int op  = (y >> 3) & 1;
        const int seg = y >> 4;
        const int my  = y & 7;
        const float* A = (op ? val : src) + (size_t)seg * KV_SEG;
        const float* W = (op ? Wv : Wk) + (size_t)seg * KV_SEG * HD;
        float* C = (op ? vpart : kpart) + (size_t)seg * 1024 * HD;
        gemm_body<false, false>(A, W, nullptr, C, S, HD, KV_SEG, D_LLM, blockIdx.x, my);
    } else {
        gemm_body<true, true>(tgt, Wq, bq, Cq, ML, HD, D_MODEL, D_MODEL, blockIdx.x, y - 32);
    }
}

// combine split-K partials: out = tf32(part0 + part1 + bias)
__global__ __launch_bounds__(256)
void kv_combine_kernel(const float* __restrict__ kpart, const float* __restrict__ bk,
                       float* __restrict__ kout,
                       const float* __restrict__ vpart, const float* __restrict__ bv,
                       float* __restrict__ vout, int n)
{
    const int n4 = n >> 2;
    const int stride = gridDim.x * blockDim.x;
    const size_t off = (size_t)1024 * HD;
    for (int i = blockIdx.x * blockDim.x + threadIdx.x; i < n4; i += stride) {
        const int col4 = (i << 2) & (HD - 1);
        float4 kb = *(const float4*)(bk + col4);
        float4 vb = *(const float4*)(bv + col4);
        float4 k0 = ((const float4*)kpart)[i];
        float4 k1 = ((const float4*)(kpart + off))[i];
        float4 v0 = ((const float4*)vpart)[i];
        float4 v1 = ((const float4*)(vpart + off))[i];
        uint4 ko, vo;
        ko.x = f32_to_tf32(k0.x + k1.x + kb.x);
        ko.y = f32_to_tf32(k0.y + k1.y + kb.y);
        ko.z = f32_to_tf32(k0.z + k1.z + kb.z);
        ko.w = f32_to_tf32(k0.w + k1.w + kb.w);
        vo.x = f32_to_tf32(v0.x + v1.x + vb.x);
        vo.y = f32_to_tf32(v0.y + v1.y + vb.y);
        vo.z = f32_to_tf32(v0.z + v1.z + vb.z);
        vo.w = f32_to_tf32(v0.w + v1.w + vb.w);
        ((uint4*)kout)[i] = ko;
        ((uint4*)vout)[i] = vo;
    }
}

// ---------------------------------------------------------------------------
// Tensor-core flash attention (tf32 m16n8k8), head_dim = 64.
// One block per (b, h, 128-query tile). 256 threads = 8 warps.
// q/k/v arrive tf32-formatted -> staging is a plain bit-copy (298us proven).
// Output tf32-formatted for the O-projection.
// ---------------------------------------------------------------------------
#define QT 128
#define QK_PITCH 68
#define V_PITCH  72
#define P_PITCH  72

__global__ __launch_bounds__(256, 2)
void attn_tc_kernel(const float* __restrict__ q, const float* __restrict__ k,
                    const float* __restrict__ v, float* __restrict__ o_out,
                    const float* __restrict__ alpha, const float* __restrict__ beta,
                    int S)
{
    extern __shared__ uint32_t smu[];
    uint32_t* Ks = smu;
    uint32_t* Vs = Ks + 64 * QK_PITCH;
    uint32_t* Ps = Vs + 64 * V_PITCH;

    const int tid  = threadIdx.x;
    const int lane = tid & 31;
    const int warp = tid >> 5;
    const int grp  = lane >> 2;
    const int tig  = lane & 3;

    const int l0 = blockIdx.x * QT;
    const int b  = blockIdx.y >> 4;
    const int h  = blockIdx.y & 15;

    const float scale = alpha[0] * beta[0] * 0.125f;

    const float* qbase = q + ((size_t)(b * L_DIM + l0)) * HD + h * D_KEYS;
    #pragma unroll
    for (int p = 0; p < 8; p++) {
        const int idx = p * 256 + tid;
        const int row = idx >> 4;
        const int e4  = (idx & 15) << 2;
        uint4 t = *(const uint4*)(qbase + (size_t)row * HD + e4);
        *(uint4*)(Ps + row * P_PITCH + e4) = t;
    }
    __syncthreads();

    uint32_t qf[8][4];
    {
        const int qrow = warp * 16 + grp;
        #pragma unroll
        for (int ks = 0; ks < 8; ks++) {
            qf[ks][0] = Ps[qrow * P_PITCH + ks * 8 + tig];
            qf[ks][1] = Ps[(qrow + 8) * P_PITCH + ks * 8 + tig];
            qf[ks][2] = Ps[qrow * P_PITCH + ks * 8 + tig + 4];
            qf[ks][3] = Ps[(qrow + 8) * P_PITCH + ks * 8 + tig + 4];
        }
    }

    float m0r = -1e30f, m1r = -1e30f, l0r = 0.0f, l1r = 0.0f;
    float oa[8][4];
    #pragma unroll
    for (int nt = 0; nt < 8; nt++)
        #pragma unroll
        for (int r = 0; r < 4; r++) oa[nt][r] = 0.0f;

    const int nTiles = (S + 63) >> 6;
    for (int ts = 0; ts < nTiles; ts++) {
        const int s0 = ts * 64;
        __syncthreads();

        const float* kb2 = k + (size_t)s0 * HD + h * D_KEYS;
        const float* vb2 = v + (size_t)s0 * HD + h * D_KEYS;
        #pragma unroll
        for (int p = 0; p < 4; p++) {
            const int idx = p * 256 + tid;
            const int j  = idx >> 4;
            const int e4 = (idx & 15) << 2;
            uint4 tk, tv;
            if (s0 + j < S) {
                tk = *(const uint4*)(kb2 + (size_t)j * HD + e4);
                tv = *(const uint4*)(vb2 + (size_t)j * HD + e4);
            } else {
                tk = make_uint4(0u, 0u, 0u, 0u);
                tv = tk;
            }
            *(uint4*)(Ks + j * QK_PITCH + e4) = tk;
            *(uint4*)(Vs + j * V_PITCH + e4) = tv;
        }
        __syncthreads();

        float sc[8][4];
        #pragma unroll
        for (int nt = 0; nt < 8; nt++)
            #pragma unroll
            for (int r = 0; r < 4; r++) sc[nt][r] = 0.0f;

        #pragma unroll
        for (int ks = 0; ks < 8; ks++) {
            #pragma unroll
            for (int nt = 0; nt < 8; nt++) {
                const uint32_t b0v = Ks[(nt * 8 + grp) * QK_PITCH + ks * 8 + tig];
                const uint32_t b1v = Ks[(nt * 8 + grp) * QK_PITCH + ks * 8 + tig + 4];
                MMA_TF32(sc[nt], qf[ks], b0v, b1v);
            }
        }

        #pragma unroll
        for (int nt = 0; nt < 8; nt++) {
            const int c0 = s0 + nt * 8 + 2 * tig;
            const bool v0 = c0 < S, v1 = (c0 + 1) < S;
            sc[nt][0] = v0 ? sc[nt][0] * scale : -1e30f;
            sc[nt][1] = v1 ? sc[nt][1] * scale : -1e30f;
            sc[nt][2] = v0 ? sc[nt][2] * scale : -1e30f;
            sc[nt][3] = v1 ? sc[nt][3] * scale : -1e30f;
        }

        float mt0 = -1e30f, mt1 = -1e30f;
        #pragma unroll
        for (int nt = 0; nt < 8; nt++) {
            mt0 = fmaxf(mt0, fmaxf(sc[nt][0], sc[nt][1]));
            mt1 = fmaxf(mt1, fmaxf(sc[nt][2], sc[nt][3]));
        }
        mt0 = fmaxf(mt0, __shfl_xor_sync(0xffffffffu, mt0, 1));
        mt0 = fmaxf(mt0, __shfl_xor_sync(0xffffffffu, mt0, 2));
        mt1 = fmaxf(mt1, __shfl_xor_sync(0xffffffffu, mt1, 1));
        mt1 = fmaxf(mt1, __shfl_xor_sync(0xffffffffu, mt1, 2));

        const float mn0 = fmaxf(m0r, mt0);
        const float mn1 = fmaxf(m1r, mt1);
        const float fac0 = __expf(m0r - mn0);
        const float fac1 = __expf(m1r - mn1);
        m0r = mn0; m1r = mn1;
        l0r *= fac0; l1r *= fac1;
        #pragma unroll
        for (int nt = 0; nt < 8; nt++) {
            oa[nt][0] *= fac0; oa[nt][1] *= fac0;
            oa[nt][2] *= fac1; oa[nt][3] *= fac1;
        }

        float rs0 = 0.0f, rs1 = 0.0f;
        #pragma unroll
        for (int nt = 0; nt < 8; nt++) {
            sc[nt][0] = __expf(sc[nt][0] - mn0);
            sc[nt][1] = __expf(sc[nt][1] - mn0);
            sc[nt][2] = __expf(sc[nt][2] - mn1);
            sc[nt][3] = __expf(sc[nt][3] - mn1);
            rs0 += sc[nt][0] + sc[nt][1];
            rs1 += sc[nt][2] + sc[nt][3];
        }
        rs0 += __shfl_xor_sync(0xffffffffu, rs0, 1);
        rs0 += __shfl_xor_sync(0xffffffffu, rs0, 2);
        rs1 += __shfl_xor_sync(0xffffffffu, rs1, 1);
        rs1 += __shfl_xor_sync(0xffffffffu, rs1, 2);
        l0r += rs0; l1r += rs1;

        {
            const int pr0 = warp * 16 + grp;
            #pragma unroll
            for (int nt = 0; nt < 8; nt++) {
                uint2 p01 = make_uint2(f32_to_tf32(sc[nt][0]), f32_to_tf32(sc[nt][1]));
                uint2 p23 = make_uint2(f32_to_tf32(sc[nt][2]), f32_to_tf32(sc[nt][3]));
                *(uint2*)&Ps[pr0 * P_PITCH + nt * 8 + 2 * tig] = p01;
                *(uint2*)&Ps[(pr0 + 8) * P_PITCH + nt * 8 + 2 * tig] = p23;
            }
        }
        __syncwarp();

        #pragma unroll
        for (int ks = 0; ks < 8; ks++) {
            uint32_t af[4];
            const int pr0 = warp * 16 + grp;
            af[0] = Ps[pr0 * P_PITCH + ks * 8 + tig];
            af[1] = Ps[(pr0 + 8) * P_PITCH + ks * 8 + tig];
            af[2] = Ps[pr0 * P_PITCH + ks * 8 + tig + 4];
            af[3] = Ps[(pr0 + 8) * P_PITCH + ks * 8 + tig + 4];
            #pragma unroll
            for (int nt = 0; nt < 8; nt++) {
                const uint32_t b0v = Vs[(ks * 8 + tig) * V_PITCH + nt * 8 + grp];
                const uint32_t b1v = Vs[(ks * 8 + tig + 4) * V_PITCH + nt * 8 + grp];
                MMA_TF32(oa[nt], af, b0v, b1v);
            }
        }
    }

    // normalize + store, tf32-formatted for the O-projection
    const float inv0 = 1.0f / l0r;
    const float inv1 = 1.0f / l1r;
    float* ob = o_out + ((size_t)(b * L_DIM + l0 + warp * 16 + grp)) * HD + h * D_KEYS;
    #pragma unroll
    for (int nt = 0; nt < 8; nt++) {
        const int col = nt * 8 + 2 * tig;
        uint2 o0 = make_uint2(f32_to_tf32(oa[nt][0] * inv0), f32_to_tf32(oa[nt][1] * inv0));
        uint2 o1 = make_uint2(f32_to_tf32(oa[nt][2] * inv1), f32_to_tf32(oa[nt][3] * inv1));
        *(uint2*)(ob + col) = o0;
        *(uint2*)(ob + (size_t)8 * HD + col) = o1;
    }
}

// ---------------------------------------------------------------------------
// Launch
// ---------------------------------------------------------------------------
extern "C" void kernel_launch(void* const* d_in, const int* in_sizes, int n_in,
                              void* d_out, int out_size)
{
    const float* target = (const float*)d_in[0];
    const float* source = (const float*)d_in[1];
    const float* value  = (const float*)d_in[2];
    const float* Wq = (const float*)d_in[3];
    const float* bq = (const float*)d_in[4];
    const float* Wk = (const float*)d_in[5];
    const float* bk = (const float*)d_in[6];
    const float* Wv = (const float*)d_in[7];
    const float* bv = (const float*)d_in[8];
    const float* Wo = (const float*)d_in[9];
    const float* bo = (const float*)d_in[10];
    const float* alpha = (const float*)d_in[11];
    const float* beta  = (const float*)d_in[12];
    float* out = (float*)d_out;

    const int S = in_sizes[1] / D_LLM;   // 1000

    float *qb, *kb, *vb, *ab, *kpart, *vpart;
    cudaGetSymbolAddress((void**)&qb, g_q);
    cudaGetSymbolAddress((void**)&kb, g_k);
    cudaGetSymbolAddress((void**)&vb, g_v);
    cudaGetSymbolAddress((void**)&ab, g_attn);
    cudaGetSymbolAddress((void**)&kpart, g_kpart);
    cudaGetSymbolAddress((void**)&vpart, g_vpart);

    dim3 blk(256);

    // Q projection + K/V split-K projections in ONE launch (768 CTAs).
    // KV CTAs (2x iterations) placed at low blockIdx.y to front-load them.
    gemm_qkv_kernel<<<dim3(HD / BNT, 96), blk>>>(
        target, Wq, bq, qb, source, Wk, kpart, value, Wv, vpart, S);
    // combine partials + bias -> tf32-formatted K/V
    kv_combine_kernel<<<dim3(256), blk>>>(kpart, bk, kb, vpart, bv, vb, S * HD);

    // fused tensor-core attention (bit-copy staging; output tf32-formatted)
    const size_t asmem = (64 * QK_PITCH + 64 * V_PITCH + QT * P_PITCH) * sizeof(uint32_t);
    cudaFuncSetAttribute(attn_tc_kernel, cudaFuncAttributeMaxDynamicSharedMemorySize, (int)asmem);
    attn_tc_kernel<<<dim3(L_DIM / QT, B_DIM * N_HEADS), blk, asmem>>>(
        qb, kb, vb, ab, alpha, beta, S);

    // out = attn @ Wo + bo   (true fp32 output)
    gemm_tf32_out_kernel<<<dim3(D_LLM / BNT, ML / BMT), blk>>>(ab, Wo, bo, out, ML, D_LLM, D_MODEL);
}

// round 17
// speedup vs baseline: 1.4013x; 1.2779x over previous
#include <cuda_runtime.h>
#include <cuda_fp16.h>
#include <cstdint>
#include <cstring>

// ---------------------------------------------------------------------------
// Problem constants
// ---------------------------------------------------------------------------
#define B_DIM 8
#define L_DIM 1024
#define D_MODEL 1024
#define N_HEADS 16
#define D_KEYS 64
#define D_LLM 4096
#define HD 1024           // N_HEADS * D_KEYS
#define ML (B_DIM * L_DIM) // 8192
#define KV_SEG 2048       // split-K segment for K/V projections

// Scratch (device globals: allocation-free contract)
__device__ float g_q[ML * HD];
__device__ float g_k[1024 * HD];
__device__ float g_v[1024 * HD];
__device__ __half g_attn_h[ML * HD];          // attention output, fp16
__device__ uint32_t g_wo_p[(HD / 2) * D_LLM]; // Wo packed: [k/2][n] = half2{W[2i][n],W[2i+1][n]}
__device__ float g_kpart[2 * 1024 * HD];
__device__ float g_vpart[2 * 1024 * HD];

__device__ __forceinline__ uint32_t f32_to_tf32(float x) {
    uint32_t r;
    asm("cvt.rna.tf32.f32 %0, %1;" : "=r"(r) : "f"(x));
    return r;
}
__device__ __forceinline__ uint32_t h2_to_u32(__half2 h) {
    uint32_t r;
    memcpy(&r, &h, 4);
    return r;
}
__device__ __forceinline__ uint32_t smem_u32(const void* p) {
    uint32_t a;
    asm("{ .reg .u64 t; cvta.to.shared.u64 t, %1; cvt.u32.u64 %0, t; }" : "=r"(a) : "l"(p));
    return a;
}
__device__ __forceinline__ void cp_async16(uint32_t dst, const void* src, bool pred) {
    const int sz = pred ? 16 : 0;
    asm volatile("cp.async.cg.shared.global [%0], [%1], 16, %2;"
                 :: "r"(dst), "l"(src), "r"(sz) : "memory");
}
__device__ __forceinline__ void cp_async_commit() {
    asm volatile("cp.async.commit_group;" ::: "memory");
}
template <int N>
__device__ __forceinline__ void cp_async_wait() {
    asm volatile("cp.async.wait_group %0;" :: "n"(N) : "memory");
}

#define MMA_TF32(d, a, b0v, b1v)                                               \
    asm volatile(                                                              \
        "mma.sync.aligned.m16n8k8.row.col.f32.tf32.tf32.f32 "                  \
        "{%0,%1,%2,%3}, {%4,%5,%6,%7}, {%8,%9}, {%0,%1,%2,%3};"                \
        : "+f"((d)[0]), "+f"((d)[1]), "+f"((d)[2]), "+f"((d)[3])               \
        : "r"((a)[0]), "r"((a)[1]), "r"((a)[2]), "r"((a)[3]),                  \
          "r"(b0v), "r"(b1v))

#define MMA_F16(d, a, b0v, b1v)                                                \
    asm volatile(                                                              \
        "mma.sync.aligned.m16n8k16.row.col.f32.f16.f16.f32 "                   \
        "{%0,%1,%2,%3}, {%4,%5,%6,%7}, {%8,%9}, {%0,%1,%2,%3};"                \
        : "+f"((d)[0]), "+f"((d)[1]), "+f"((d)[2]), "+f"((d)[3])               \
        : "r"((a)[0]), "r"((a)[1]), "r"((a)[2]), "r"((a)[3]),                  \
          "r"(b0v), "r"(b1v))

// ---------------------------------------------------------------------------
// TF32 tensor-core GEMM, cp.async 4-stage pipeline (proven config).
// ---------------------------------------------------------------------------
#define BMT 128
#define BNT 128
#define BKT 8
#define APITCH 12
#define BPITCH 136
#define STAGES 4

template <bool CVT_OUT, bool ADD_BIAS>
__device__ __forceinline__
void gemm_body(const float* __restrict__ A, const float* __restrict__ W,
               const float* __restrict__ bias, float* __restrict__ C,
               int M, int N, int K, int lda, int bx, int by)
{
    __shared__ float As[STAGES][BMT][APITCH];
    __shared__ float Bs[STAGES][BKT][BPITCH];

    const int tid  = threadIdx.x;
    const int lane = tid & 31;
    const int warp = tid >> 5;
    const int wm = (warp >> 2) * 64;
    const int wn = (warp & 3) * 32;
    const int grp = lane >> 2;
    const int tig = lane & 3;

    const int m0 = by * BMT;
    const int n0 = bx * BNT;

    const int a_row = tid >> 1;
    const int a_k   = (tid & 1) << 2;
    const int b_k   = tid >> 5;
    const int b_n   = (tid & 31) << 2;

    const bool a_ok = (m0 + a_row) < M;
    const float* a_src = A + (size_t)(m0 + a_row) * lda + a_k;
    const float* b_src = W + (size_t)b_k * N + n0 + b_n;

    const uint32_t a_dst0 = smem_u32(&As[0][a_row][a_k]);
    const uint32_t b_dst0 = smem_u32(&Bs[0][b_k][b_n]);
    const uint32_t a_stride = (uint32_t)(BMT * APITCH * 4);
    const uint32_t b_stride = (uint32_t)(BKT * BPITCH * 4);

    float acc[4][4][4];
    #pragma unroll
    for (int i = 0; i < 4; i++)
        #pragma unroll
        for (int j = 0; j < 4; j++)
            #pragma unroll
            for (int r = 0; r < 4; r++) acc[i][j][r] = 0.0f;

    const int nk = K / BKT;

    #pragma unroll
    for (int s = 0; s < STAGES - 1; s++) {
        if (s < nk) {
            cp_async16(a_dst0 + s * a_stride, a_src + (size_t)s * BKT, a_ok);
            cp_async16(b_dst0 + s * b_stride, b_src + (size_t)s * BKT * N, true);
        }
        cp_async_commit();
    }

    for (int kt = 0; kt < nk; kt++) {
        const int cur = kt & (STAGES - 1);
        cp_async_wait<STAGES - 2>();
        __syncthreads();

        {
            const int kn = kt + STAGES - 1;
            if (kn < nk) {
                const int st = kn & (STAGES - 1);
                cp_async16(a_dst0 + st * a_stride, a_src + (size_t)kn * BKT, a_ok);
                cp_async16(b_dst0 + st * b_stride, b_src + (size_t)kn * BKT * N, true);
            }
            cp_async_commit();
        }

        uint32_t af[4][4], bf[4][2];
        #pragma unroll
        for (int tm = 0; tm < 4; tm++) {
            const int rb = wm + tm * 16 + grp;
            af[tm][0] = f32_to_tf32(As[cur][rb][tig]);
            af[tm][1] = f32_to_tf32(As[cur][rb + 8][tig]);
            af[tm][2] = f32_to_tf32(As[cur][rb][tig + 4]);
            af[tm][3] = f32_to_tf32(As[cur][rb + 8][tig + 4]);
        }
        #pragma unroll
        for (int tn = 0; tn < 4; tn++) {
            const int nb = wn + tn * 8 + grp;
            bf[tn][0] = f32_to_tf32(Bs[cur][tig][nb]);
            bf[tn][1] = f32_to_tf32(Bs[cur][tig + 4][nb]);
        }

        #pragma unroll
        for (int tm = 0; tm < 4; tm++)
            #pragma unroll
            for (int tn = 0; tn < 4; tn++)
                MMA_TF32(acc[tm][tn], af[tm], bf[tn][0], bf[tn][1]);
    }

    #pragma unroll
    for (int tm = 0; tm < 4; tm++) {
        const int row  = m0 + wm + tm * 16 + grp;
        const int row2 = row + 8;
        #pragma unroll
        for (int tn = 0; tn < 4; tn++) {
            const int col = n0 + wn + tn * 8 + 2 * tig;
            float b0v = 0.0f, b1v = 0.0f;
            if (ADD_BIAS) { b0v = bias[col]; b1v = bias[col + 1]; }
            float o0 = acc[tm][tn][0] + b0v, o1 = acc[tm][tn][1] + b1v;
            float o2 = acc[tm][tn][2] + b0v, o3 = acc[tm][tn][3] + b1v;
            if (CVT_OUT) {
                o0 = __uint_as_float(f32_to_tf32(o0));
                o1 = __uint_as_float(f32_to_tf32(o1));
                o2 = __uint_as_float(f32_to_tf32(o2));
                o3 = __uint_as_float(f32_to_tf32(o3));
            }
            if (row < M)  *(float2*)(C + (size_t)row * N + col)  = make_float2(o0, o1);
            if (row2 < M) *(float2*)(C + (size_t)row2 * N + col) = make_float2(o2, o3);
        }
    }
}

// Merged Q-projection + split-K K/V projections. grid = (8, 96).
__global__ __launch_bounds__(256, 2)
void gemm_qkv_kernel(const float* __restrict__ tgt, const float* __restrict__ Wq,
                     const float* __restrict__ bq, float* __restrict__ Cq,
                     const float* __restrict__ src, const float* __restrict__ Wk,
                     float* __restrict__ kpart,
                     const float* __restrict__ val, const float* __restrict__ Wv,
                     float* __restrict__ vpart,
                     int S)
{
    const int y = blockIdx.y;
    if (y < 32) {
        const int op  = (y >> 3) & 1;
        const int seg = y >> 4;
        const int my  = y & 7;
        const float* A = (op ? val : src) + (size_t)seg * KV_SEG;
        const float* W = (op ? Wv : Wk) + (size_t)seg * KV_SEG * HD;
        float* C = (op ? vpart : kpart) + (size_t)seg * 1024 * HD;
        gemm_body<false, false>(A, W, nullptr, C, S, HD, KV_SEG, D_LLM, blockIdx.x, my);
    } else {
        gemm_body<true, true>(tgt, Wq, bq, Cq, ML, HD, D_MODEL, D_MODEL, blockIdx.x, y - 32);
    }
}

// combine split-K partials: out = tf32(part0 + part1 + bias)
__global__ __launch_bounds__(256)
void kv_combine_kernel(const float* __restrict__ kpart, const float* __restrict__ bk,
                       float* __restrict__ kout,
                       const float* __restrict__ vpart, const float* __restrict__ bv,
                       float* __restrict__ vout, int n)
{
    const int n4 = n >> 2;
    const int stride = gridDim.x * blockDim.x;
    const size_t off = (size_t)1024 * HD;
    for (int i = blockIdx.x * blockDim.x + threadIdx.x; i < n4; i += stride) {
        const int col4 = (i << 2) & (HD - 1);
        float4 kb = *(const float4*)(bk + col4);
        float4 vb = *(const float4*)(bv + col4);
        float4 k0 = ((const float4*)kpart)[i];
        float4 k1 = ((const float4*)(kpart + off))[i];
        float4 v0 = ((const float4*)vpart)[i];
        float4 v1 = ((const float4*)(vpart + off))[i];
        uint4 ko, vo;
        ko.x = f32_to_tf32(k0.x + k1.x + kb.x);
        ko.y = f32_to_tf32(k0.y + k1.y + kb.y);
        ko.z = f32_to_tf32(k0.z + k1.z + kb.z);
        ko.w = f32_to_tf32(k0.w + k1.w + kb.w);
        vo.x = f32_to_tf32(v0.x + v1.x + vb.x);
        vo.y = f32_to_tf32(v0.y + v1.y + vb.y);
        vo.z = f32_to_tf32(v0.z + v1.z + vb.z);
        vo.w = f32_to_tf32(v0.w + v1.w + vb.w);
        ((uint4*)kout)[i] = ko;
        ((uint4*)vout)[i] = vo;
    }
}

// ---------------------------------------------------------------------------
// Wo pack prepass: g_wo_p[i][n] = half2{ Wo[2i][n], Wo[2i+1][n] }
// ---------------------------------------------------------------------------
__global__ __launch_bounds__(256)
void wo_pack_kernel(const float* __restrict__ Wo, uint32_t* __restrict__ Wp)
{
    const int total = (HD / 2) * (D_LLM / 4);   // 524288
    const int stride = gridDim.x * blockDim.x;
    for (int idx = blockIdx.x * blockDim.x + threadIdx.x; idx < total; idx += stride) {
        const int i = idx / (D_LLM / 4);
        const int g = idx % (D_LLM / 4);
        float4 r0 = *(const float4*)(Wo + (size_t)(2 * i) * D_LLM + g * 4);
        float4 r1 = *(const float4*)(Wo + (size_t)(2 * i + 1) * D_LLM + g * 4);
        uint4 o;
        o.x = h2_to_u32(__floats2half2_rn(r0.x, r1.x));
        o.y = h2_to_u32(__floats2half2_rn(r0.y, r1.y));
        o.z = h2_to_u32(__floats2half2_rn(r0.z, r1.z));
        o.w = h2_to_u32(__floats2half2_rn(r0.w, r1.w));
        *(uint4*)(Wp + (size_t)i * D_LLM + g * 4) = o;
    }
}

// ---------------------------------------------------------------------------
// FP16 tensor-core GEMM for the O-projection (m16n8k16), cp.async 4-stage:
//   C[M,N] = A_h[M,K] @ Wp + bias   (A fp16, Wp packed half2, acc/out fp32)
// 128x128 CTA tile, BK=16 halves (8 u32 rows), 256 threads, warp tile 64x32.
// ---------------------------------------------------------------------------
__global__ __launch_bounds__(256, 2)
void gemm_fp16_out_kernel(const __half* __restrict__ A, const uint32_t* __restrict__ Wp,
                          const float* __restrict__ bias, float* __restrict__ C,
                          int M, int N, int K)
{
    __shared__ uint32_t As[STAGES][BMT][APITCH];   // [row][u32 k-pair 0..7 +pad]
    __shared__ uint32_t Bs[STAGES][BKT][BPITCH];   // [packed-k row][n u32]

    const int tid  = threadIdx.x;
    const int lane = tid & 31;
    const int warp = tid >> 5;
    const int wm = (warp >> 2) * 64;
    const int wn = (warp & 3) * 32;
    const int grp = lane >> 2;
    const int tig = lane & 3;

    const int m0 = blockIdx.y * BMT;
    const int n0 = blockIdx.x * BNT;

    const int a_row = tid >> 1;            // 0..127
    const int a_u   = (tid & 1) << 2;      // u32 slot 0 or 4
    const int b_k   = tid >> 5;            // 0..7 packed rows
    const int b_n   = (tid & 31) << 2;     // 0..124 u32

    const bool a_ok = (m0 + a_row) < M;
    const __half* a_src = A + (size_t)(m0 + a_row) * K + a_u * 2;   // halves
    const uint32_t* b_src = Wp + (size_t)b_k * N + n0 + b_n;

    const uint32_t a_dst0 = smem_u32(&As[0][a_row][a_u]);
    const uint32_t b_dst0 = smem_u32(&Bs[0][b_k][b_n]);
    const uint32_t a_stride = (uint32_t)(BMT * APITCH * 4);
    const uint32_t b_stride = (uint32_t)(BKT * BPITCH * 4);

    float acc[4][4][4];
    #pragma unroll
    for (int i = 0; i < 4; i++)
        #pragma unroll
        for (int j = 0; j < 4; j++)
            #pragma unroll
            for (int r = 0; r < 4; r++) acc[i][j][r] = 0.0f;

    const int nk = K / 16;   // 64 iterations

    #pragma unroll
    for (int s = 0; s < STAGES - 1; s++) {
        if (s < nk) {
            cp_async16(a_dst0 + s * a_stride, a_src + (size_t)s * 16, a_ok);
            cp_async16(b_dst0 + s * b_stride, b_src + (size_t)s * 8 * N, true);
        }
        cp_async_commit();
    }

    for (int kt = 0; kt < nk; kt++) {
        const int cur = kt & (STAGES - 1);
        cp_async_wait<STAGES - 2>();
        __syncthreads();

        {
            const int kn = kt + STAGES - 1;
            if (kn < nk) {
                const int st = kn & (STAGES - 1);
                cp_async16(a_dst0 + st * a_stride, a_src + (size_t)kn * 16, a_ok);
                cp_async16(b_dst0 + st * b_stride, b_src + (size_t)kn * 8 * N, true);
            }
            cp_async_commit();
        }

        // fragments: plain u32 loads (native fp16 pairs), NO cvt
        uint32_t af[4][4], bf[4][2];
        #pragma unroll
        for (int tm = 0; tm < 4; tm++) {
            const int rb = wm + tm * 16 + grp;
            af[tm][0] = As[cur][rb][tig];          // row grp,   k 2tig,2tig+1
            af[tm][1] = As[cur][rb + 8][tig];      // row grp+8
            af[tm][2] = As[cur][rb][tig + 4];      // row grp,   k 2tig+8,+9
            af[tm][3] = As[cur][rb + 8][tig + 4];
        }
        #pragma unroll
        for (int tn = 0; tn < 4; tn++) {
            const int nb = wn + tn * 8 + grp;
            bf[tn][0] = Bs[cur][tig][nb];          // k rows 2tig,2tig+1
            bf[tn][1] = Bs[cur][tig + 4][nb];      // k rows 2tig+8,+9
        }

        #pragma unroll
        for (int tm = 0; tm < 4; tm++)
            #pragma unroll
            for (int tn = 0; tn < 4; tn++)
                MMA_F16(acc[tm][tn], af[tm], bf[tn][0], bf[tn][1]);
    }

    #pragma unroll
    for (int tm = 0; tm < 4; tm++) {
        const int row  = m0 + wm + tm * 16 + grp;
        const int row2 = row + 8;
        #pragma unroll
        for (int tn = 0; tn < 4; tn++) {
            const int col = n0 + wn + tn * 8 + 2 * tig;
            const float b0v = bias[col];
            const float b1v = bias[col + 1];
            if (row < M) {
                float2 o = make_float2(acc[tm][tn][0] + b0v, acc[tm][tn][1] + b1v);
                *(float2*)(C + (size_t)row * N + col) = o;
            }
            if (row2 < M) {
                float2 o = make_float2(acc[tm][tn][2] + b0v, acc[tm][tn][3] + b1v);
                *(float2*)(C + (size_t)row2 * N + col) = o;
            }
        }
    }
}

// ---------------------------------------------------------------------------
// Tensor-core flash attention (tf32 m16n8k8), head_dim = 64. (Proven 298us.)
// Output written as fp16 for the fp16 O-projection.
// ---------------------------------------------------------------------------
#define QT 128
#define QK_PITCH 68
#define V_PITCH  72
#define P_PITCH  72

__global__ __launch_bounds__(256, 2)
void attn_tc_kernel(const float* __restrict__ q, const float* __restrict__ k,
                    const float* __restrict__ v, __half* __restrict__ o_out,
                    const float* __restrict__ alpha, const float* __restrict__ beta,
                    int S)
{
    extern __shared__ uint32_t smu[];
    uint32_t* Ks = smu;
    uint32_t* Vs = Ks + 64 * QK_PITCH;
    uint32_t* Ps = Vs + 64 * V_PITCH;

    const int tid  = threadIdx.x;
    const int lane = tid & 31;
    const int warp = tid >> 5;
    const int grp  = lane >> 2;
    const int tig  = lane & 3;

    const int l0 = blockIdx.x * QT;
    const int b  = blockIdx.y >> 4;
    const int h  = blockIdx.y & 15;

    const float scale = alpha[0] * beta[0] * 0.125f;

    const float* qbase = q + ((size_t)(b * L_DIM + l0)) * HD + h * D_KEYS;
    #pragma unroll
    for (int p = 0; p < 8; p++) {
        const int idx = p * 256 + tid;
        const int row = idx >> 4;
        const int e4  = (idx & 15) << 2;
        uint4 t = *(const uint4*)(qbase + (size_t)row * HD + e4);
        *(uint4*)(Ps + row * P_PITCH + e4) = t;
    }
    __syncthreads();

    uint32_t qf[8][4];
    {
        const int qrow = warp * 16 + grp;
        #pragma unroll
        for (int ks = 0; ks < 8; ks++) {
            qf[ks][0] = Ps[qrow * P_PITCH + ks * 8 + tig];
            qf[ks][1] = Ps[(qrow + 8) * P_PITCH + ks * 8 + tig];
            qf[ks][2] = Ps[qrow * P_PITCH + ks * 8 + tig + 4];
            qf[ks][3] = Ps[(qrow + 8) * P_PITCH + ks * 8 + tig + 4];
        }
    }

    float m0r = -1e30f, m1r = -1e30f, l0r = 0.0f, l1r = 0.0f;
    float oa[8][4];
    #pragma unroll
    for (int nt = 0; nt < 8; nt++)
        #pragma unroll
        for (int r = 0; r < 4; r++) oa[nt][r] = 0.0f;

    const int nTiles = (S + 63) >> 6;
    for (int ts = 0; ts < nTiles; ts++) {
        const int s0 = ts * 64;
        __syncthreads();

        const float* kb2 = k + (size_t)s0 * HD + h * D_KEYS;
        const float* vb2 = v + (size_t)s0 * HD + h * D_KEYS;
        #pragma unroll
        for (int p = 0; p < 4; p++) {
            const int idx = p * 256 + tid;
            const int j  = idx >> 4;
            const int e4 = (idx & 15) << 2;
            uint4 tk, tv;
            if (s0 + j < S) {
                tk = *(const uint4*)(kb2 + (size_t)j * HD + e4);
                tv = *(const uint4*)(vb2 + (size_t)j * HD + e4);
            } else {
                tk = make_uint4(0u, 0u, 0u, 0u);
                tv = tk;
            }
            *(uint4*)(Ks + j * QK_PITCH + e4) = tk;
            *(uint4*)(Vs + j * V_PITCH + e4) = tv;
        }
        __syncthreads();

        float sc[8][4];
        #pragma unroll
        for (int nt = 0; nt < 8; nt++)
            #pragma unroll
            for (int r = 0; r < 4; r++) sc[nt][r] = 0.0f;

        #pragma unroll
        for (int ks = 0; ks < 8; ks++) {
            #pragma unroll
            for (int nt = 0; nt < 8; nt++) {
                const uint32_t b0v = Ks[(nt * 8 + grp) * QK_PITCH + ks * 8 + tig];
                const uint32_t b1v = Ks[(nt * 8 + grp) * QK_PITCH + ks * 8 + tig + 4];
                MMA_TF32(sc[nt], qf[ks], b0v, b1v);
            }
        }

        #pragma unroll
        for (int nt = 0; nt < 8; nt++) {
            const int c0 = s0 + nt * 8 + 2 * tig;
            const bool v0 = c0 < S, v1 = (c0 + 1) < S;
            sc[nt][0] = v0 ? sc[nt][0] * scale : -1e30f;
            sc[nt][1] = v1 ? sc[nt][1] * scale : -1e30f;
            sc[nt][2] = v0 ? sc[nt][2] * scale : -1e30f;
            sc[nt][3] = v1 ? sc[nt][3] * scale : -1e30f;
        }

        float mt0 = -1e30f, mt1 = -1e30f;
        #pragma unroll
        for (int nt = 0; nt < 8; nt++) {
            mt0 = fmaxf(mt0, fmaxf(sc[nt][0], sc[nt][1]));
            mt1 = fmaxf(mt1, fmaxf(sc[nt][2], sc[nt][3]));
        }
        mt0 = fmaxf(mt0, __shfl_xor_sync(0xffffffffu, mt0, 1));
        mt0 = fmaxf(mt0, __shfl_xor_sync(0xffffffffu, mt0, 2));
        mt1 = fmaxf(mt1, __shfl_xor_sync(0xffffffffu, mt1, 1));
        mt1 = fmaxf(mt1, __shfl_xor_sync(0xffffffffu, mt1, 2));

        const float mn0 = fmaxf(m0r, mt0);
        const float mn1 = fmaxf(m1r, mt1);
        const float fac0 = __expf(m0r - mn0);
        const float fac1 = __expf(m1r - mn1);
        m0r = mn0; m1r = mn1;
        l0r *= fac0; l1r *= fac1;
        #pragma unroll
        for (int nt = 0; nt < 8; nt++) {
            oa[nt][0] *= fac0; oa[nt][1] *= fac0;
            oa[nt][2] *= fac1; oa[nt][3] *= fac1;
        }

        float rs0 = 0.0f, rs1 = 0.0f;
        #pragma unroll
        for (int nt = 0; nt < 8; nt++) {
            sc[nt][0] = __expf(sc[nt][0] - mn0);
            sc[nt][1] = __expf(sc[nt][1] - mn0);
            sc[nt][2] = __expf(sc[nt][2] - mn1);
            sc[nt][3] = __expf(sc[nt][3] - mn1);
            rs0 += sc[nt][0] + sc[nt][1];
            rs1 += sc[nt][2] + sc[nt][3];
        }
        rs0 += __shfl_xor_sync(0xffffffffu, rs0, 1);
        rs0 += __shfl_xor_sync(0xffffffffu, rs0, 2);
        rs1 += __shfl_xor_sync(0xffffffffu, rs1, 1);
        rs1 += __shfl_xor_sync(0xffffffffu, rs1, 2);
        l0r += rs0; l1r += rs1;

        {
            const int pr0 = warp * 16 + grp;
            #pragma unroll
            for (int nt = 0; nt < 8; nt++) {
                uint2 p01 = make_uint2(f32_to_tf32(sc[nt][0]), f32_to_tf32(sc[nt][1]));
                uint2 p23 = make_uint2(f32_to_tf32(sc[nt][2]), f32_to_tf32(sc[nt][3]));
                *(uint2*)&Ps[pr0 * P_PITCH + nt * 8 + 2 * tig] = p01;
                *(uint2*)&Ps[(pr0 + 8) * P_PITCH + nt * 8 + 2 * tig] = p23;
            }
        }
        __syncwarp();

        #pragma unroll
        for (int ks = 0; ks < 8; ks++) {
            uint32_t af[4];
            const int pr0 = warp * 16 + grp;
            af[0] = Ps[pr0 * P_PITCH + ks * 8 + tig];
            af[1] = Ps[(pr0 + 8) * P_PITCH + ks * 8 + tig];
            af[2] = Ps[pr0 * P_PITCH + ks * 8 + tig + 4];
            af[3] = Ps[(pr0 + 8) * P_PITCH + ks * 8 + tig + 4];
            #pragma unroll
            for (int nt = 0; nt < 8; nt++) {
                const uint32_t b0v = Vs[(ks * 8 + tig) * V_PITCH + nt * 8 + grp];
                const uint32_t b1v = Vs[(ks * 8 + tig + 4) * V_PITCH + nt * 8 + grp];
                MMA_TF32(oa[nt], af, b0v, b1v);
            }
        }
    }

    // normalize + store as fp16 for the O-projection
    const float inv0 = 1.0f / l0r;
    const float inv1 = 1.0f / l1r;
    __half* ob = o_out + ((size_t)(b * L_DIM + l0 + warp * 16 + grp)) * HD + h * D_KEYS;
    #pragma unroll
    for (int nt = 0; nt < 8; nt++) {
        const int col = nt * 8 + 2 * tig;
        *(__half2*)(ob + col) = __floats2half2_rn(oa[nt][0] * inv0, oa[nt][1] * inv0);
        *(__half2*)(ob + (size_t)8 * HD + col) = __floats2half2_rn(oa[nt][2] * inv1, oa[nt][3] * inv1);
    }
}

// ---------------------------------------------------------------------------
// Launch
// ---------------------------------------------------------------------------
extern "C" void kernel_launch(void* const* d_in, const int* in_sizes, int n_in,
                              void* d_out, int out_size)
{
    const float* target = (const float*)d_in[0];
    const float* source = (const float*)d_in[1];
    const float* value  = (const float*)d_in[2];
    const float* Wq = (const float*)d_in[3];
    const float* bq = (const float*)d_in[4];
    const float* Wk = (const float*)d_in[5];
    const float* bk = (const float*)d_in[6];
    const float* Wv = (const float*)d_in[7];
    const float* bv = (const float*)d_in[8];
    const float* Wo = (const float*)d_in[9];
    const float* bo = (const float*)d_in[10];
    const float* alpha = (const float*)d_in[11];
    const float* beta  = (const float*)d_in[12];
    float* out = (float*)d_out;

    const int S = in_sizes[1] / D_LLM;   // 1000

    float *qb, *kb, *vb, *kpart, *vpart;
    __half* ab;
    uint32_t* wop;
    cudaGetSymbolAddress((void**)&qb, g_q);
    cudaGetSymbolAddress((void**)&kb, g_k);
    cudaGetSymbolAddress((void**)&vb, g_v);
    cudaGetSymbolAddress((void**)&ab, g_attn_h);
    cudaGetSymbolAddress((void**)&wop, g_wo_p);
    cudaGetSymbolAddress((void**)&kpart, g_kpart);
    cudaGetSymbolAddress((void**)&vpart, g_vpart);

    dim3 blk(256);

    // pack Wo into fp16 k-pair-interleaved layout
    wo_pack_kernel<<<dim3(512), blk>>>(Wo, wop);

    // Q projection + K/V split-K projections in ONE launch (768 CTAs)
    gemm_qkv_kernel<<<dim3(HD / BNT, 96), blk>>>(
        target, Wq, bq, qb, source, Wk, kpart, value, Wv, vpart, S);
    // combine partials + bias -> tf32-formatted K/V
    kv_combine_kernel<<<dim3(256), blk>>>(kpart, bk, kb, vpart, bv, vb, S * HD);

    // fused tensor-core attention (bit-copy staging; fp16 output)
    const size_t asmem = (64 * QK_PITCH + 64 * V_PITCH + QT * P_PITCH) * sizeof(uint32_t);
    cudaFuncSetAttribute(attn_tc_kernel, cudaFuncAttributeMaxDynamicSharedMemorySize, (int)asmem);
    attn_tc_kernel<<<dim3(L_DIM / QT, B_DIM * N_HEADS), blk, asmem>>>(
        qb, kb, vb, ab, alpha, beta, S);

    // out = attn @ Wo + bo   (fp16 operands, fp32 accumulate/output)
    gemm_fp16_out_kernel<<<dim3(D_LLM / BNT, ML / BMT), blk>>>(
        ab, wop, bo, out, ML, D_LLM, D_MODEL);
}